// round 1
// baseline (speedup 1.0000x reference)
#include <cuda_runtime.h>
#include <cuda_bf16.h>
#include <math.h>

// Problem constants (fixed by the dataset: S=1024, B=16, I=D=1024, L=2)
#define S_LEN 1024
#define BATCH 16
#define DIM   1024
#define GDIM  (4 * DIM)      // 4096 gate channels
#define NLAYERS 2
#define EPS 1e-6f

// ---------------------------------------------------------------------------
// Scratch (device globals — no allocation allowed in kernel_launch)
// ---------------------------------------------------------------------------
__device__ float g_pre[(size_t)S_LEN * BATCH * GDIM];     // 268 MB: gate pre-activations (reused by both layers)
__device__ float g_h0out[(size_t)S_LEN * BATCH * DIM];    // 67 MB: layer-0 hidden outputs (input to layer 1)

// ---------------------------------------------------------------------------
// GEMM: C[M,N] = A[M,K] @ W[N,K]^T + bias[N]
// Both operands are K-major (row-major with K contiguous) -> symmetric loads.
// 128x128 block tile, BK=8, 16x16 threads, 8x8 per-thread strided tile.
// ---------------------------------------------------------------------------
#define BM 128
#define BN 128
#define BK 8

__global__ __launch_bounds__(256, 2)
void sgemm_bias_kernel(const float* __restrict__ A,
                       const float* __restrict__ W,
                       const float* __restrict__ bias,
                       float* __restrict__ C,
                       int M, int N, int K)
{
    __shared__ float As[BK][BM + 4];
    __shared__ float Bs[BK][BN + 4];

    const int tid = threadIdx.x;          // 0..255
    const int tx  = tid & 15;             // 0..15 (N direction)
    const int ty  = tid >> 4;             // 0..15 (M direction)

    const int bm = blockIdx.y * BM;
    const int bn = blockIdx.x * BN;

    const float* Ab = A + (size_t)bm * K;
    const float* Wb = W + (size_t)bn * K;

    // Loader mapping: each thread loads one float4 of A and one float4 of W per tile.
    const int lr = tid >> 1;              // row within tile: 0..127
    const int lk = (tid & 1) * 4;         // k offset: 0 or 4

    float acc[8][8];
#pragma unroll
    for (int i = 0; i < 8; i++)
#pragma unroll
        for (int j = 0; j < 8; j++) acc[i][j] = 0.0f;

    for (int k0 = 0; k0 < K; k0 += BK) {
        float4 av = *reinterpret_cast<const float4*>(Ab + (size_t)lr * K + k0 + lk);
        float4 bv = *reinterpret_cast<const float4*>(Wb + (size_t)lr * K + k0 + lk);
        As[lk + 0][lr] = av.x; As[lk + 1][lr] = av.y;
        As[lk + 2][lr] = av.z; As[lk + 3][lr] = av.w;
        Bs[lk + 0][lr] = bv.x; Bs[lk + 1][lr] = bv.y;
        Bs[lk + 2][lr] = bv.z; Bs[lk + 3][lr] = bv.w;
        __syncthreads();

#pragma unroll
        for (int k = 0; k < BK; k++) {
            float ar[8], br[8];
#pragma unroll
            for (int i = 0; i < 8; i++) ar[i] = As[k][i * 16 + ty];   // strided tile: conflict-free
#pragma unroll
            for (int j = 0; j < 8; j++) br[j] = Bs[k][j * 16 + tx];
#pragma unroll
            for (int i = 0; i < 8; i++)
#pragma unroll
                for (int j = 0; j < 8; j++)
                    acc[i][j] = fmaf(ar[i], br[j], acc[i][j]);
        }
        __syncthreads();
    }

    // Epilogue: strided thread tile -> C[bm + i*16 + ty][bn + j*16 + tx]
    float bcache[8];
#pragma unroll
    for (int j = 0; j < 8; j++) bcache[j] = bias[bn + j * 16 + tx];

#pragma unroll
    for (int i = 0; i < 8; i++) {
        const size_t row = (size_t)(bm + i * 16 + ty);
        float* Crow = C + row * N + bn;
#pragma unroll
        for (int j = 0; j < 8; j++) {
            Crow[j * 16 + tx] = acc[i][j] + bcache[j];
        }
    }
}

// ---------------------------------------------------------------------------
// Elementwise sLSTM scan over time. One thread per (b, d) lane.
// pre: [S, B, 4D] with gates at offsets {0,D,2D,3D}+d.
// Adds r*h inside the scan so arbitrary r is handled correctly.
// ---------------------------------------------------------------------------
__global__ __launch_bounds__(256)
void slstm_scan_kernel(const float* __restrict__ pre,     // [S,B,4D]
                       const float* __restrict__ r,       // [4D]
                       const float* __restrict__ h0,      // [L,B,D]
                       const float* __restrict__ extra0,  // [L,B,3D]
                       int layer,
                       float* __restrict__ hout,          // [S,B,D]
                       float* __restrict__ hf,            // [L,B,D]
                       float* __restrict__ extraf)        // [L,B,3D]
{
    const int tid = blockIdx.x * blockDim.x + threadIdx.x;   // 0 .. B*D-1
    const int d = tid & (DIM - 1);
    const int b = tid >> 10;                                  // tid / DIM

    const float rz = r[0 * DIM + d];
    const float ri = r[1 * DIM + d];
    const float rf = r[2 * DIM + d];
    const float ro = r[3 * DIM + d];

    const size_t lbd  = (size_t)layer * BATCH * DIM + (size_t)b * DIM;
    const size_t lb3d = (size_t)layer * BATCH * 3 * DIM + (size_t)b * 3 * DIM;

    float h = h0[lbd + d];
    float c = extra0[lb3d + 0 * DIM + d];
    float n = extra0[lb3d + 1 * DIM + d];
    float m = extra0[lb3d + 2 * DIM + d];

    const float* p = pre + (size_t)b * GDIM + d;
    const size_t strideT = (size_t)BATCH * GDIM;
    float* ho = hout + (size_t)b * DIM + d;
    const size_t strideO = (size_t)BATCH * DIM;

    for (int t = 0; t < S_LEN; t++) {
        const float zp = p[0 * DIM] + rz * h;
        const float ip = p[1 * DIM] + ri * h;
        const float fp = p[2 * DIM] + rf * h;
        const float op = p[3 * DIM] + ro * h;

        const float zt = tanhf(zp);
        const float ot = 1.0f / (1.0f + expf(-op));
        const float fm = fp + m;
        const float mn = fmaxf(fm, ip);
        const float ft = expf(fm - mn);
        const float it = expf(ip - mn);

        c = ft * c + it * zt;
        n = ft * n + it;
        m = mn;
        h = ot * (c / (fabsf(n) + EPS));

        *ho = h;
        p  += strideT;
        ho += strideO;
    }

    hf[lbd + d] = h;
    extraf[lb3d + 0 * DIM + d] = c;
    extraf[lb3d + 1 * DIM + d] = n;
    extraf[lb3d + 2 * DIM + d] = m;
}

// ---------------------------------------------------------------------------
// Launch
// Inputs (metadata order): input, h0, extra0, W0, b0, r0, W1, b1, r1
// Output packing: output[S,B,D] || h_f[L,B,D] || extra_f[L,B,3D]
// ---------------------------------------------------------------------------
extern "C" void kernel_launch(void* const* d_in, const int* in_sizes, int n_in,
                              void* d_out, int out_size)
{
    const float* input  = (const float*)d_in[0];
    const float* h0     = (const float*)d_in[1];
    const float* extra0 = (const float*)d_in[2];
    const float* W0     = (const float*)d_in[3];
    const float* b0     = (const float*)d_in[4];
    const float* r0     = (const float*)d_in[5];
    const float* W1     = (const float*)d_in[6];
    const float* b1     = (const float*)d_in[7];
    const float* r1     = (const float*)d_in[8];

    float* out     = (float*)d_out;                                    // [S,B,D]
    float* hf      = out + (size_t)S_LEN * BATCH * DIM;                // [L,B,D]
    float* extraf  = hf + (size_t)NLAYERS * BATCH * DIM;               // [L,B,3D]

    float* pre;
    float* h0out;
    cudaGetSymbolAddress((void**)&pre,   g_pre);
    cudaGetSymbolAddress((void**)&h0out, g_h0out);

    const int M = S_LEN * BATCH;   // 16384
    const int N = GDIM;            // 4096
    const int K = DIM;             // 1024

    dim3 gemmGrid(N / BN, M / BM);   // (32, 128)
    dim3 gemmBlock(256);
    dim3 scanGrid((BATCH * DIM) / 256);
    dim3 scanBlock(256);

    // Layer 0: pre = input @ W0^T + b0 ; scan -> h0out + finals[0]
    sgemm_bias_kernel<<<gemmGrid, gemmBlock>>>(input, W0, b0, pre, M, N, K);
    slstm_scan_kernel<<<scanGrid, scanBlock>>>(pre, r0, h0, extra0, 0,
                                               h0out, hf, extraf);

    // Layer 1: pre = h0out @ W1^T + b1 ; scan -> out + finals[1]
    sgemm_bias_kernel<<<gemmGrid, gemmBlock>>>(h0out, W1, b1, pre, M, N, K);
    slstm_scan_kernel<<<scanGrid, scanBlock>>>(pre, r1, h0, extra0, 1,
                                               out, hf, extraf);
}

// round 3
// speedup vs baseline: 2.9456x; 2.9456x over previous
#include <cuda_runtime.h>
#include <cuda_bf16.h>
#include <math.h>
#include <stdint.h>

// Problem constants (fixed: S=1024, B=16, I=D=1024, L=2)
#define S_LEN 1024
#define BATCH 16
#define DIM   1024
#define GDIM  (4 * DIM)       // 4096
#define KDIM  1024
#define MROWS (S_LEN * BATCH) // 16384
#define EPS 1e-6f

// ---------------------------------------------------------------------------
// Device scratch (no allocation allowed in kernel_launch)
// ---------------------------------------------------------------------------
__device__ float         g_pre[(size_t)S_LEN * BATCH * GDIM];  // 268 MB
__device__ __nv_bfloat16 g_ahi[(size_t)MROWS * KDIM];          // 33.5 MB
__device__ __nv_bfloat16 g_alo[(size_t)MROWS * KDIM];
__device__ __nv_bfloat16 g_whi[(size_t)GDIM * KDIM];           // 8.4 MB
__device__ __nv_bfloat16 g_wlo[(size_t)GDIM * KDIM];

// ---------------------------------------------------------------------------
// PTX helpers — base-target only (NO tcgen05: harness emits compute_103 PTX)
// ---------------------------------------------------------------------------
__device__ __forceinline__ uint32_t smem_u32(const void* p) {
    uint32_t a;
    asm("{ .reg .u64 t; cvta.to.shared.u64 t, %1; cvt.u32.u64 %0, t; }"
        : "=r"(a) : "l"(p));
    return a;
}
__device__ __forceinline__ void cp16(uint32_t dst, const void* src) {
    asm volatile("cp.async.cg.shared.global [%0], [%1], 16;"
                 :: "r"(dst), "l"(src));
}
__device__ __forceinline__ void ldsm_x4(uint32_t& r0, uint32_t& r1,
                                        uint32_t& r2, uint32_t& r3,
                                        uint32_t addr) {
    asm volatile("ldmatrix.sync.aligned.m8n8.x4.shared.b16 {%0,%1,%2,%3}, [%4];"
                 : "=r"(r0), "=r"(r1), "=r"(r2), "=r"(r3) : "r"(addr));
}
__device__ __forceinline__ void mma_bf16(float* d, const uint32_t* a,
                                         uint32_t b0, uint32_t b1) {
    asm volatile(
        "mma.sync.aligned.m16n8k16.row.col.f32.bf16.bf16.f32 "
        "{%0,%1,%2,%3}, {%4,%5,%6,%7}, {%8,%9}, {%0,%1,%2,%3};"
        : "+f"(d[0]), "+f"(d[1]), "+f"(d[2]), "+f"(d[3])
        : "r"(a[0]), "r"(a[1]), "r"(a[2]), "r"(a[3]), "r"(b0), "r"(b1));
}

// Swizzle: rows are 64B (32 bf16); XOR the 16B-segment index with (row>>1)&3
// so the 8 rows touched by one ldmatrix phase cover all 32 banks.
__device__ __forceinline__ uint32_t swz_addr(uint32_t plane_base, int row, int seg) {
    return plane_base + (uint32_t)(row * 64) + ((uint32_t)((seg ^ ((row >> 1) & 3)) << 4));
}

// ---------------------------------------------------------------------------
// fp32 -> (bf16 hi, bf16 lo) split kernel. n must be a multiple of 4.
// ---------------------------------------------------------------------------
__global__ __launch_bounds__(256)
void split_kernel(const float* __restrict__ src,
                  __nv_bfloat16* __restrict__ hi,
                  __nv_bfloat16* __restrict__ lo, int n)
{
    int i = (blockIdx.x * 256 + threadIdx.x) * 4;
    if (i >= n) return;
    float4 v = *reinterpret_cast<const float4*>(src + i);
    __nv_bfloat16 h0 = __float2bfloat16(v.x);
    __nv_bfloat16 h1 = __float2bfloat16(v.y);
    __nv_bfloat16 h2 = __float2bfloat16(v.z);
    __nv_bfloat16 h3 = __float2bfloat16(v.w);
    __nv_bfloat16 l0 = __float2bfloat16(v.x - __bfloat162float(h0));
    __nv_bfloat16 l1 = __float2bfloat16(v.y - __bfloat162float(h1));
    __nv_bfloat16 l2 = __float2bfloat16(v.z - __bfloat162float(h2));
    __nv_bfloat16 l3 = __float2bfloat16(v.w - __bfloat162float(h3));
    __nv_bfloat162* hi2 = reinterpret_cast<__nv_bfloat162*>(hi + i);
    __nv_bfloat162* lo2 = reinterpret_cast<__nv_bfloat162*>(lo + i);
    hi2[0] = __nv_bfloat162(h0, h1);
    hi2[1] = __nv_bfloat162(h2, h3);
    lo2[0] = __nv_bfloat162(l0, l1);
    lo2[1] = __nv_bfloat162(l2, l3);
}

// ---------------------------------------------------------------------------
// HMMA GEMM: C[M=16384, N=4096] = A[M,K=1024] @ W[N,K]^T + bias[N]
// fp32 via bf16 split: C = Ahi*Whi + Ahi*Wlo + Alo*Whi (fp32 accum).
// CTA 128x128, 8 warps (4M x 2N -> 32x64 warp tile), K-chunk 32,
// 3-stage cp.async pipeline, ldmatrix + mma.sync.m16n8k16.
// ---------------------------------------------------------------------------
#define KCHUNK 32
#define NCHUNK (KDIM / KCHUNK)       // 32
#define PLANE  8192                  // 128 rows * 64 bytes
#define STAGE_BYTES (4 * PLANE)      // Ahi, Alo, Whi, Wlo = 32 KB
#define STAGES 3
#define GEMM_SMEM (STAGES * STAGE_BYTES)   // 96 KB

__device__ __forceinline__ void load_chunk(uint32_t stage_base,
                                           const __nv_bfloat16* Ah,
                                           const __nv_bfloat16* Al,
                                           const __nv_bfloat16* Bh,
                                           const __nv_bfloat16* Bl,
                                           int k0, int tid)
{
    // 4 planes x 128 rows x 4 segs(16B). 2048 cp16 / 256 threads = 8 each.
#pragma unroll
    for (int p = 0; p < 4; p++) {
        const __nv_bfloat16* src = (p == 0) ? Ah : (p == 1) ? Al : (p == 2) ? Bh : Bl;
#pragma unroll
        for (int h = 0; h < 2; h++) {
            int it = tid + h * 256;          // 0..511
            int row = it >> 2;
            int seg = it & 3;
            cp16(swz_addr(stage_base + p * PLANE, row, seg),
                 src + (size_t)row * KDIM + k0 + seg * 8);
        }
    }
}

__global__ __launch_bounds__(256, 1)
void gemm_tc_kernel(const __nv_bfloat16* __restrict__ Ahi,
                    const __nv_bfloat16* __restrict__ Alo,
                    const __nv_bfloat16* __restrict__ Whi,
                    const __nv_bfloat16* __restrict__ Wlo,
                    const float* __restrict__ bias,
                    float* __restrict__ C)
{
    extern __shared__ __align__(1024) char smem[];
    const uint32_t sbase = smem_u32(smem);
    const int tid  = threadIdx.x;
    const int wid  = tid >> 5;
    const int lane = tid & 31;
    const int warp_m = wid & 3;     // 4 warps in M: 32 rows each
    const int warp_n = wid >> 2;    // 2 warps in N: 64 cols each
    const int bm = blockIdx.y * 128;
    const int bn = blockIdx.x * 128;

    const __nv_bfloat16* Ah = Ahi + (size_t)bm * KDIM;
    const __nv_bfloat16* Al = Alo + (size_t)bm * KDIM;
    const __nv_bfloat16* Bh = Whi + (size_t)bn * KDIM;
    const __nv_bfloat16* Bl = Wlo + (size_t)bn * KDIM;

    float acc[2][8][4];
#pragma unroll
    for (int i = 0; i < 2; i++)
#pragma unroll
        for (int j = 0; j < 8; j++)
#pragma unroll
            for (int k = 0; k < 4; k++) acc[i][j][k] = 0.0f;

    // Prologue: stages 0,1
    load_chunk(sbase + 0 * STAGE_BYTES, Ah, Al, Bh, Bl, 0, tid);
    asm volatile("cp.async.commit_group;");
    load_chunk(sbase + 1 * STAGE_BYTES, Ah, Al, Bh, Bl, KCHUNK, tid);
    asm volatile("cp.async.commit_group;");

    // Precompute lane-dependent row/seg pieces
    const int a_lrow = lane & 15;          // row within m16 tile
    const int a_lseg = lane >> 4;          // 0/1 -> k8 half
    const int b_lrow = (lane & 7) + ((lane >> 4) << 3);  // row within n16 pair
    const int b_lseg = (lane >> 3) & 1;    // k8 half

    for (int i = 0; i < NCHUNK; i++) {
        if (i + 1 < NCHUNK) { asm volatile("cp.async.wait_group 1;"); }
        else                { asm volatile("cp.async.wait_group 0;"); }
        __syncthreads();

        if (i + 2 < NCHUNK) {
            load_chunk(sbase + (uint32_t)((i + 2) % STAGES) * STAGE_BYTES,
                       Ah, Al, Bh, Bl, (i + 2) * KCHUNK, tid);
            asm volatile("cp.async.commit_group;");
        }

        const uint32_t st = sbase + (uint32_t)(i % STAGES) * STAGE_BYTES;

#pragma unroll
        for (int ks = 0; ks < 2; ks++) {
            uint32_t a[2][4], bhr[4][4], blr[4][4];

            // A_hi fragments (2 m16 tiles)
#pragma unroll
            for (int ti = 0; ti < 2; ti++) {
                int row = warp_m * 32 + ti * 16 + a_lrow;
                int seg = ks * 2 + a_lseg;
                ldsm_x4(a[ti][0], a[ti][1], a[ti][2], a[ti][3],
                        swz_addr(st + 0 * PLANE, row, seg));
            }
            // W_hi fragments (4 x (pair of n8 groups))
#pragma unroll
            for (int jj = 0; jj < 4; jj++) {
                int row = warp_n * 64 + jj * 16 + b_lrow;
                int seg = ks * 2 + b_lseg;
                ldsm_x4(bhr[jj][0], bhr[jj][1], bhr[jj][2], bhr[jj][3],
                        swz_addr(st + 2 * PLANE, row, seg));
            }
            // hi * hi
#pragma unroll
            for (int ti = 0; ti < 2; ti++)
#pragma unroll
                for (int jj = 0; jj < 4; jj++) {
                    mma_bf16(acc[ti][2 * jj + 0], a[ti], bhr[jj][0], bhr[jj][1]);
                    mma_bf16(acc[ti][2 * jj + 1], a[ti], bhr[jj][2], bhr[jj][3]);
                }
            // W_lo fragments, hi * lo
#pragma unroll
            for (int jj = 0; jj < 4; jj++) {
                int row = warp_n * 64 + jj * 16 + b_lrow;
                int seg = ks * 2 + b_lseg;
                ldsm_x4(blr[jj][0], blr[jj][1], blr[jj][2], blr[jj][3],
                        swz_addr(st + 3 * PLANE, row, seg));
            }
#pragma unroll
            for (int ti = 0; ti < 2; ti++)
#pragma unroll
                for (int jj = 0; jj < 4; jj++) {
                    mma_bf16(acc[ti][2 * jj + 0], a[ti], blr[jj][0], blr[jj][1]);
                    mma_bf16(acc[ti][2 * jj + 1], a[ti], blr[jj][2], blr[jj][3]);
                }
            // A_lo fragments (overwrite a), lo * hi
#pragma unroll
            for (int ti = 0; ti < 2; ti++) {
                int row = warp_m * 32 + ti * 16 + a_lrow;
                int seg = ks * 2 + a_lseg;
                ldsm_x4(a[ti][0], a[ti][1], a[ti][2], a[ti][3],
                        swz_addr(st + 1 * PLANE, row, seg));
            }
#pragma unroll
            for (int ti = 0; ti < 2; ti++)
#pragma unroll
                for (int jj = 0; jj < 4; jj++) {
                    mma_bf16(acc[ti][2 * jj + 0], a[ti], bhr[jj][0], bhr[jj][1]);
                    mma_bf16(acc[ti][2 * jj + 1], a[ti], bhr[jj][2], bhr[jj][3]);
                }
        }
    }

    // Epilogue: acc layout — thread holds rows (lane>>2, +8), cols (lane&3)*2,+1
    const int mrow0 = bm + warp_m * 32 + (lane >> 2);
    const int col0  = bn + warp_n * 64 + (lane & 3) * 2;
#pragma unroll
    for (int ti = 0; ti < 2; ti++) {
#pragma unroll
        for (int g = 0; g < 8; g++) {
            int col = col0 + g * 8;
            float bb0 = bias[col];
            float bb1 = bias[col + 1];
            int r0 = mrow0 + ti * 16;
            float2 v0 = make_float2(acc[ti][g][0] + bb0, acc[ti][g][1] + bb1);
            float2 v1 = make_float2(acc[ti][g][2] + bb0, acc[ti][g][3] + bb1);
            *reinterpret_cast<float2*>(C + (size_t)r0 * GDIM + col) = v0;
            *reinterpret_cast<float2*>(C + (size_t)(r0 + 8) * GDIM + col) = v1;
        }
    }
}

// ---------------------------------------------------------------------------
// Elementwise sLSTM scan with depth-4 register prefetch.
// EMIT_BF16: layer-0 writes h as bf16 hi/lo split (feeds GEMM1 directly);
// otherwise writes fp32 (final output).
// ---------------------------------------------------------------------------
template <bool EMIT_BF16>
__global__ __launch_bounds__(128)
void slstm_scan_kernel(const float* __restrict__ pre,     // [S,B,4D]
                       const float* __restrict__ r,       // [4D]
                       const float* __restrict__ h0,      // [L,B,D]
                       const float* __restrict__ extra0,  // [L,B,3D]
                       int layer,
                       float* __restrict__ out_f32,       // [S,B,D] (or null)
                       __nv_bfloat16* __restrict__ out_hi,
                       __nv_bfloat16* __restrict__ out_lo,
                       float* __restrict__ hf,            // [L,B,D]
                       float* __restrict__ extraf)        // [L,B,3D]
{
    const int tid = blockIdx.x * 128 + threadIdx.x;   // 0..B*D-1
    const int d = tid & (DIM - 1);
    const int b = tid >> 10;

    const float rz = r[0 * DIM + d];
    const float ri = r[1 * DIM + d];
    const float rf = r[2 * DIM + d];
    const float ro = r[3 * DIM + d];

    const size_t lbd  = (size_t)layer * BATCH * DIM + (size_t)b * DIM;
    const size_t lb3d = (size_t)layer * BATCH * 3 * DIM + (size_t)b * 3 * DIM;

    float h = h0[lbd + d];
    float c = extra0[lb3d + 0 * DIM + d];
    float n = extra0[lb3d + 1 * DIM + d];
    float m = extra0[lb3d + 2 * DIM + d];

    const float* p = pre + (size_t)b * GDIM + d;
    const size_t strideT = (size_t)BATCH * GDIM;

    float pz[4], pi[4], pf4[4], po[4];
#pragma unroll
    for (int j = 0; j < 4; j++) {
        pz[j]  = p[0 * DIM];
        pi[j]  = p[1 * DIM];
        pf4[j] = p[2 * DIM];
        po[j]  = p[3 * DIM];
        p += strideT;
    }

    size_t outIdx = (size_t)b * DIM + d;
    const size_t strideO = (size_t)BATCH * DIM;

    for (int t = 0; t < S_LEN; t += 4) {
        const bool more = (t + 4 < S_LEN);
#pragma unroll
        for (int j = 0; j < 4; j++) {
            const float zp = pz[j]  + rz * h;
            const float ip = pi[j]  + ri * h;
            const float fp = pf4[j] + rf * h;
            const float op = po[j]  + ro * h;

            if (more) {           // prefetch t+4+j, overlaps transcendentals
                pz[j]  = p[0 * DIM];
                pi[j]  = p[1 * DIM];
                pf4[j] = p[2 * DIM];
                po[j]  = p[3 * DIM];
                p += strideT;
            }

            const float zt = tanhf(zp);
            const float ot = 1.0f / (1.0f + expf(-op));
            const float fm = fp + m;
            const float mn = fmaxf(fm, ip);
            const float ft = expf(fm - mn);
            const float it = expf(ip - mn);

            c = ft * c + it * zt;
            n = ft * n + it;
            m = mn;
            h = ot * (c / (fabsf(n) + EPS));

            if (EMIT_BF16) {
                __nv_bfloat16 hh = __float2bfloat16(h);
                out_hi[outIdx] = hh;
                out_lo[outIdx] = __float2bfloat16(h - __bfloat162float(hh));
            } else {
                out_f32[outIdx] = h;
            }
            outIdx += strideO;
        }
    }

    hf[lbd + d] = h;
    extraf[lb3d + 0 * DIM + d] = c;
    extraf[lb3d + 1 * DIM + d] = n;
    extraf[lb3d + 2 * DIM + d] = m;
}

// ---------------------------------------------------------------------------
// Launch. Inputs: input, h0, extra0, W0, b0, r0, W1, b1, r1
// Output: output[S,B,D] || h_f[L,B,D] || extra_f[L,B,3D]
// ---------------------------------------------------------------------------
extern "C" void kernel_launch(void* const* d_in, const int* in_sizes, int n_in,
                              void* d_out, int out_size)
{
    const float* input  = (const float*)d_in[0];
    const float* h0     = (const float*)d_in[1];
    const float* extra0 = (const float*)d_in[2];
    const float* W0     = (const float*)d_in[3];
    const float* b0     = (const float*)d_in[4];
    const float* r0     = (const float*)d_in[5];
    const float* W1     = (const float*)d_in[6];
    const float* b1     = (const float*)d_in[7];
    const float* r1     = (const float*)d_in[8];

    float* out    = (float*)d_out;
    float* hf     = out + (size_t)S_LEN * BATCH * DIM;
    float* extraf = hf + (size_t)2 * BATCH * DIM;

    float* pre;           cudaGetSymbolAddress((void**)&pre,  g_pre);
    __nv_bfloat16* ahi;   cudaGetSymbolAddress((void**)&ahi,  g_ahi);
    __nv_bfloat16* alo;   cudaGetSymbolAddress((void**)&alo,  g_alo);
    __nv_bfloat16* whi;   cudaGetSymbolAddress((void**)&whi,  g_whi);
    __nv_bfloat16* wlo;   cudaGetSymbolAddress((void**)&wlo,  g_wlo);

    cudaFuncSetAttribute(gemm_tc_kernel,
                         cudaFuncAttributeMaxDynamicSharedMemorySize, GEMM_SMEM);

    const int nA = MROWS * KDIM;   // 16.7M
    const int nW = GDIM * KDIM;    // 4.2M

    dim3 gemmGrid(GDIM / 128, MROWS / 128);   // (32, 128)
    dim3 scanGrid((BATCH * DIM) / 128);       // 128

    // ---- Layer 0 ----
    split_kernel<<<nA / 1024, 256>>>(input, ahi, alo, nA);
    split_kernel<<<nW / 1024, 256>>>(W0, whi, wlo, nW);
    gemm_tc_kernel<<<gemmGrid, 256, GEMM_SMEM>>>(ahi, alo, whi, wlo, b0, pre);
    // scan0 consumes pre; GEMM0 has fully consumed ahi/alo, so scan0 reuses them
    slstm_scan_kernel<true><<<scanGrid, 128>>>(pre, r0, h0, extra0, 0,
                                               nullptr, ahi, alo, hf, extraf);

    // ---- Layer 1 ----
    split_kernel<<<nW / 1024, 256>>>(W1, whi, wlo, nW);
    gemm_tc_kernel<<<gemmGrid, 256, GEMM_SMEM>>>(ahi, alo, whi, wlo, b1, pre);
    slstm_scan_kernel<false><<<scanGrid, 128>>>(pre, r1, h0, extra0, 1,
                                                out, nullptr, nullptr, hf, extraf);
}

// round 4
// speedup vs baseline: 3.6948x; 1.2543x over previous
#include <cuda_runtime.h>
#include <cuda_bf16.h>
#include <math.h>
#include <stdint.h>

// Problem constants (fixed: S=1024, B=16, I=D=1024, L=2)
#define S_LEN 1024
#define BATCH 16
#define DIM   1024
#define GDIM  (4 * DIM)       // 4096
#define KDIM  1024
#define MROWS (S_LEN * BATCH) // 16384
#define EPS 1e-6f

// ---------------------------------------------------------------------------
// Device scratch (no allocation allowed in kernel_launch)
// ---------------------------------------------------------------------------
__device__ float         g_pre[(size_t)S_LEN * BATCH * GDIM];  // 268 MB
__device__ __nv_bfloat16 g_ahi[(size_t)MROWS * KDIM];          // 33.5 MB
__device__ __nv_bfloat16 g_alo[(size_t)MROWS * KDIM];
__device__ __nv_bfloat16 g_whi[(size_t)GDIM * KDIM];           // 8.4 MB
__device__ __nv_bfloat16 g_wlo[(size_t)GDIM * KDIM];

// ---------------------------------------------------------------------------
// PTX helpers — base-target only (NO tcgen05: harness emits compute_103 PTX)
// ---------------------------------------------------------------------------
__device__ __forceinline__ uint32_t smem_u32(const void* p) {
    uint32_t a;
    asm("{ .reg .u64 t; cvta.to.shared.u64 t, %1; cvt.u32.u64 %0, t; }"
        : "=r"(a) : "l"(p));
    return a;
}
__device__ __forceinline__ void cp16(uint32_t dst, const void* src) {
    asm volatile("cp.async.cg.shared.global [%0], [%1], 16;"
                 :: "r"(dst), "l"(src));
}
__device__ __forceinline__ void ldsm_x4(uint32_t& r0, uint32_t& r1,
                                        uint32_t& r2, uint32_t& r3,
                                        uint32_t addr) {
    asm volatile("ldmatrix.sync.aligned.m8n8.x4.shared.b16 {%0,%1,%2,%3}, [%4];"
                 : "=r"(r0), "=r"(r1), "=r"(r2), "=r"(r3) : "r"(addr));
}
__device__ __forceinline__ void mma_bf16(float* d, const uint32_t* a,
                                         uint32_t b0, uint32_t b1) {
    asm volatile(
        "mma.sync.aligned.m16n8k16.row.col.f32.bf16.bf16.f32 "
        "{%0,%1,%2,%3}, {%4,%5,%6,%7}, {%8,%9}, {%0,%1,%2,%3};"
        : "+f"(d[0]), "+f"(d[1]), "+f"(d[2]), "+f"(d[3])
        : "r"(a[0]), "r"(a[1]), "r"(a[2]), "r"(a[3]), "r"(b0), "r"(b1));
}

// Fast math (all rel err ~2^-21; far under the 1e-3 budget)
__device__ __forceinline__ float fast_sigmoid(float x) {
    return __fdividef(1.0f, 1.0f + __expf(-x));
}
__device__ __forceinline__ float fast_tanh(float x) {
    float e = __expf(2.0f * x);
    return __fdividef(e - 1.0f, e + 1.0f);
}

// Swizzle: rows are 64B (32 bf16); XOR the 16B-segment index with (row>>1)&3
__device__ __forceinline__ uint32_t swz_addr(uint32_t plane_base, int row, int seg) {
    return plane_base + (uint32_t)(row * 64) + ((uint32_t)((seg ^ ((row >> 1) & 3)) << 4));
}

// ---------------------------------------------------------------------------
// fp32 -> (bf16 hi, bf16 lo) split kernel. n must be a multiple of 4.
// ---------------------------------------------------------------------------
__global__ __launch_bounds__(256)
void split_kernel(const float* __restrict__ src,
                  __nv_bfloat16* __restrict__ hi,
                  __nv_bfloat16* __restrict__ lo, int n)
{
    int i = (blockIdx.x * 256 + threadIdx.x) * 4;
    if (i >= n) return;
    float4 v = *reinterpret_cast<const float4*>(src + i);
    __nv_bfloat16 h0 = __float2bfloat16(v.x);
    __nv_bfloat16 h1 = __float2bfloat16(v.y);
    __nv_bfloat16 h2 = __float2bfloat16(v.z);
    __nv_bfloat16 h3 = __float2bfloat16(v.w);
    __nv_bfloat16 l0 = __float2bfloat16(v.x - __bfloat162float(h0));
    __nv_bfloat16 l1 = __float2bfloat16(v.y - __bfloat162float(h1));
    __nv_bfloat16 l2 = __float2bfloat16(v.z - __bfloat162float(h2));
    __nv_bfloat16 l3 = __float2bfloat16(v.w - __bfloat162float(h3));
    __nv_bfloat162* hi2 = reinterpret_cast<__nv_bfloat162*>(hi + i);
    __nv_bfloat162* lo2 = reinterpret_cast<__nv_bfloat162*>(lo + i);
    hi2[0] = __nv_bfloat162(h0, h1);
    hi2[1] = __nv_bfloat162(h2, h3);
    lo2[0] = __nv_bfloat162(l0, l1);
    lo2[1] = __nv_bfloat162(l2, l3);
}

// ---------------------------------------------------------------------------
// HMMA GEMM: C[M=16384, N=4096] = A[M,K=1024] @ W[N,K]^T + bias[N]
// fp32 via bf16 split: C = Ahi*Whi + Ahi*Wlo + Alo*Whi (fp32 accum).
// CTA 128x128, 8 warps (4M x 2N -> 32x64 warp tile), K-chunk 32,
// 3-stage cp.async pipeline, 2 CTAs/SM.
// ---------------------------------------------------------------------------
#define KCHUNK 32
#define NCHUNK (KDIM / KCHUNK)       // 32
#define PLANE  8192                  // 128 rows * 64 bytes
#define STAGE_BYTES (4 * PLANE)      // Ahi, Alo, Whi, Wlo = 32 KB
#define STAGES 3
#define GEMM_SMEM (STAGES * STAGE_BYTES)   // 96 KB

__device__ __forceinline__ void load_chunk(uint32_t stage_base,
                                           const __nv_bfloat16* Ah,
                                           const __nv_bfloat16* Al,
                                           const __nv_bfloat16* Bh,
                                           const __nv_bfloat16* Bl,
                                           int k0, int tid)
{
#pragma unroll
    for (int p = 0; p < 4; p++) {
        const __nv_bfloat16* src = (p == 0) ? Ah : (p == 1) ? Al : (p == 2) ? Bh : Bl;
#pragma unroll
        for (int h = 0; h < 2; h++) {
            int it = tid + h * 256;          // 0..511
            int row = it >> 2;
            int seg = it & 3;
            cp16(swz_addr(stage_base + p * PLANE, row, seg),
                 src + (size_t)row * KDIM + k0 + seg * 8);
        }
    }
}

__global__ __launch_bounds__(256, 2)
void gemm_tc_kernel(const __nv_bfloat16* __restrict__ Ahi,
                    const __nv_bfloat16* __restrict__ Alo,
                    const __nv_bfloat16* __restrict__ Whi,
                    const __nv_bfloat16* __restrict__ Wlo,
                    const float* __restrict__ bias,
                    float* __restrict__ C)
{
    extern __shared__ __align__(1024) char smem[];
    const uint32_t sbase = smem_u32(smem);
    const int tid  = threadIdx.x;
    const int wid  = tid >> 5;
    const int lane = tid & 31;
    const int warp_m = wid & 3;     // 4 warps in M: 32 rows each
    const int warp_n = wid >> 2;    // 2 warps in N: 64 cols each
    const int bm = blockIdx.y * 128;
    const int bn = blockIdx.x * 128;

    const __nv_bfloat16* Ah = Ahi + (size_t)bm * KDIM;
    const __nv_bfloat16* Al = Alo + (size_t)bm * KDIM;
    const __nv_bfloat16* Bh = Whi + (size_t)bn * KDIM;
    const __nv_bfloat16* Bl = Wlo + (size_t)bn * KDIM;

    float acc[2][8][4];
#pragma unroll
    for (int i = 0; i < 2; i++)
#pragma unroll
        for (int j = 0; j < 8; j++)
#pragma unroll
            for (int k = 0; k < 4; k++) acc[i][j][k] = 0.0f;

    load_chunk(sbase + 0 * STAGE_BYTES, Ah, Al, Bh, Bl, 0, tid);
    asm volatile("cp.async.commit_group;");
    load_chunk(sbase + 1 * STAGE_BYTES, Ah, Al, Bh, Bl, KCHUNK, tid);
    asm volatile("cp.async.commit_group;");

    const int a_lrow = lane & 15;
    const int a_lseg = lane >> 4;
    const int b_lrow = (lane & 7) + ((lane >> 4) << 3);
    const int b_lseg = (lane >> 3) & 1;

    for (int i = 0; i < NCHUNK; i++) {
        if (i + 1 < NCHUNK) { asm volatile("cp.async.wait_group 1;"); }
        else                { asm volatile("cp.async.wait_group 0;"); }
        __syncthreads();

        if (i + 2 < NCHUNK) {
            load_chunk(sbase + (uint32_t)((i + 2) % STAGES) * STAGE_BYTES,
                       Ah, Al, Bh, Bl, (i + 2) * KCHUNK, tid);
            asm volatile("cp.async.commit_group;");
        }

        const uint32_t st = sbase + (uint32_t)(i % STAGES) * STAGE_BYTES;

#pragma unroll
        for (int ks = 0; ks < 2; ks++) {
            uint32_t a[2][4], al[2][4], w[4][4];

            // A_hi, W_hi
#pragma unroll
            for (int ti = 0; ti < 2; ti++) {
                int row = warp_m * 32 + ti * 16 + a_lrow;
                ldsm_x4(a[ti][0], a[ti][1], a[ti][2], a[ti][3],
                        swz_addr(st + 0 * PLANE, row, ks * 2 + a_lseg));
            }
#pragma unroll
            for (int jj = 0; jj < 4; jj++) {
                int row = warp_n * 64 + jj * 16 + b_lrow;
                ldsm_x4(w[jj][0], w[jj][1], w[jj][2], w[jj][3],
                        swz_addr(st + 2 * PLANE, row, ks * 2 + b_lseg));
            }
            // hi * hi
#pragma unroll
            for (int ti = 0; ti < 2; ti++)
#pragma unroll
                for (int jj = 0; jj < 4; jj++) {
                    mma_bf16(acc[ti][2 * jj + 0], a[ti], w[jj][0], w[jj][1]);
                    mma_bf16(acc[ti][2 * jj + 1], a[ti], w[jj][2], w[jj][3]);
                }
            // A_lo, lo * hi
#pragma unroll
            for (int ti = 0; ti < 2; ti++) {
                int row = warp_m * 32 + ti * 16 + a_lrow;
                ldsm_x4(al[ti][0], al[ti][1], al[ti][2], al[ti][3],
                        swz_addr(st + 1 * PLANE, row, ks * 2 + a_lseg));
            }
#pragma unroll
            for (int ti = 0; ti < 2; ti++)
#pragma unroll
                for (int jj = 0; jj < 4; jj++) {
                    mma_bf16(acc[ti][2 * jj + 0], al[ti], w[jj][0], w[jj][1]);
                    mma_bf16(acc[ti][2 * jj + 1], al[ti], w[jj][2], w[jj][3]);
                }
            // W_lo (reuse w regs), hi * lo
#pragma unroll
            for (int jj = 0; jj < 4; jj++) {
                int row = warp_n * 64 + jj * 16 + b_lrow;
                ldsm_x4(w[jj][0], w[jj][1], w[jj][2], w[jj][3],
                        swz_addr(st + 3 * PLANE, row, ks * 2 + b_lseg));
            }
#pragma unroll
            for (int ti = 0; ti < 2; ti++)
#pragma unroll
                for (int jj = 0; jj < 4; jj++) {
                    mma_bf16(acc[ti][2 * jj + 0], a[ti], w[jj][0], w[jj][1]);
                    mma_bf16(acc[ti][2 * jj + 1], a[ti], w[jj][2], w[jj][3]);
                }
        }
    }

    // Epilogue (streaming stores: C is read once by the scan, 268MB)
    const int mrow0 = bm + warp_m * 32 + (lane >> 2);
    const int col0  = bn + warp_n * 64 + (lane & 3) * 2;
#pragma unroll
    for (int ti = 0; ti < 2; ti++) {
#pragma unroll
        for (int g = 0; g < 8; g++) {
            int col = col0 + g * 8;
            float bb0 = bias[col];
            float bb1 = bias[col + 1];
            int r0 = mrow0 + ti * 16;
            float2 v0 = make_float2(acc[ti][g][0] + bb0, acc[ti][g][1] + bb1);
            float2 v1 = make_float2(acc[ti][g][2] + bb0, acc[ti][g][3] + bb1);
            __stcs(reinterpret_cast<float2*>(C + (size_t)r0 * GDIM + col), v0);
            __stcs(reinterpret_cast<float2*>(C + (size_t)(r0 + 8) * GDIM + col), v1);
        }
    }
}

// ---------------------------------------------------------------------------
// Elementwise sLSTM scan: fast math, depth-8 register prefetch (__ldcs),
// r==0 fast path (gates independent of state -> batch-computed).
// ---------------------------------------------------------------------------
#define PF 8

template <bool EMIT_BF16>
__global__ __launch_bounds__(128)
void slstm_scan_kernel(const float* __restrict__ pre,     // [S,B,4D]
                       const float* __restrict__ r,       // [4D]
                       const float* __restrict__ h0,      // [L,B,D]
                       const float* __restrict__ extra0,  // [L,B,3D]
                       int layer,
                       float* __restrict__ out_f32,       // [S,B,D] (or null)
                       __nv_bfloat16* __restrict__ out_hi,
                       __nv_bfloat16* __restrict__ out_lo,
                       float* __restrict__ hf,            // [L,B,D]
                       float* __restrict__ extraf)        // [L,B,3D]
{
    const int tid = blockIdx.x * 128 + threadIdx.x;   // 0..B*D-1
    const int d = tid & (DIM - 1);
    const int b = tid >> 10;

    const float rz = r[0 * DIM + d];
    const float ri = r[1 * DIM + d];
    const float rf = r[2 * DIM + d];
    const float ro = r[3 * DIM + d];
    const bool rzero = (rz == 0.0f) && (ri == 0.0f) && (rf == 0.0f) && (ro == 0.0f);

    const size_t lbd  = (size_t)layer * BATCH * DIM + (size_t)b * DIM;
    const size_t lb3d = (size_t)layer * BATCH * 3 * DIM + (size_t)b * 3 * DIM;

    float h = h0[lbd + d];
    float c = extra0[lb3d + 0 * DIM + d];
    float n = extra0[lb3d + 1 * DIM + d];
    float m = extra0[lb3d + 2 * DIM + d];

    const float* p = pre + (size_t)b * GDIM + d;
    const size_t strideT = (size_t)BATCH * GDIM;

    float pz[PF], pi_[PF], pf_[PF], po_[PF];
#pragma unroll
    for (int j = 0; j < PF; j++) {
        pz[j]  = __ldcs(p + 0 * DIM);
        pi_[j] = __ldcs(p + 1 * DIM);
        pf_[j] = __ldcs(p + 2 * DIM);
        po_[j] = __ldcs(p + 3 * DIM);
        p += strideT;
    }

    size_t outIdx = (size_t)b * DIM + d;
    const size_t strideO = (size_t)BATCH * DIM;

    if (rzero) {
        // Gates do not depend on state: compute transcendentals for the whole
        // batch of PF steps up front (max ILP), then do a short serial chain.
        for (int t = 0; t < S_LEN; t += PF) {
            const bool more = (t + PF < S_LEN);
            float zt[PF], ot[PF], ip[PF], fp[PF];
#pragma unroll
            for (int j = 0; j < PF; j++) {
                zt[j] = fast_tanh(pz[j]);
                ot[j] = fast_sigmoid(po_[j]);
                ip[j] = pi_[j];
                fp[j] = pf_[j];
            }
            if (more) {
#pragma unroll
                for (int j = 0; j < PF; j++) {
                    pz[j]  = __ldcs(p + 0 * DIM);
                    pi_[j] = __ldcs(p + 1 * DIM);
                    pf_[j] = __ldcs(p + 2 * DIM);
                    po_[j] = __ldcs(p + 3 * DIM);
                    p += strideT;
                }
            }
#pragma unroll
            for (int j = 0; j < PF; j++) {
                const float fm = fp[j] + m;
                const float mn = fmaxf(fm, ip[j]);
                const float ft = __expf(fm - mn);
                const float it = __expf(ip[j] - mn);
                c = ft * c + it * zt[j];
                n = ft * n + it;
                m = mn;
                h = ot[j] * __fdividef(c, fabsf(n) + EPS);
                if (EMIT_BF16) {
                    __nv_bfloat16 hh = __float2bfloat16(h);
                    out_hi[outIdx] = hh;
                    out_lo[outIdx] = __float2bfloat16(h - __bfloat162float(hh));
                } else {
                    out_f32[outIdx] = h;
                }
                outIdx += strideO;
            }
        }
    } else {
        // General path: r*h feeds back into the gates.
        for (int t = 0; t < S_LEN; t += PF) {
            const bool more = (t + PF < S_LEN);
            float bz[PF], bi[PF], bf4[PF], bo[PF];
#pragma unroll
            for (int j = 0; j < PF; j++) {
                bz[j] = pz[j]; bi[j] = pi_[j]; bf4[j] = pf_[j]; bo[j] = po_[j];
            }
            if (more) {
#pragma unroll
                for (int j = 0; j < PF; j++) {
                    pz[j]  = __ldcs(p + 0 * DIM);
                    pi_[j] = __ldcs(p + 1 * DIM);
                    pf_[j] = __ldcs(p + 2 * DIM);
                    po_[j] = __ldcs(p + 3 * DIM);
                    p += strideT;
                }
            }
#pragma unroll
            for (int j = 0; j < PF; j++) {
                const float zp = bz[j]  + rz * h;
                const float ip = bi[j]  + ri * h;
                const float fp = bf4[j] + rf * h;
                const float op = bo[j]  + ro * h;
                const float zt = fast_tanh(zp);
                const float ot = fast_sigmoid(op);
                const float fm = fp + m;
                const float mn = fmaxf(fm, ip);
                const float ft = __expf(fm - mn);
                const float it = __expf(ip - mn);
                c = ft * c + it * zt;
                n = ft * n + it;
                m = mn;
                h = ot * __fdividef(c, fabsf(n) + EPS);
                if (EMIT_BF16) {
                    __nv_bfloat16 hh = __float2bfloat16(h);
                    out_hi[outIdx] = hh;
                    out_lo[outIdx] = __float2bfloat16(h - __bfloat162float(hh));
                } else {
                    out_f32[outIdx] = h;
                }
                outIdx += strideO;
            }
        }
    }

    hf[lbd + d] = h;
    extraf[lb3d + 0 * DIM + d] = c;
    extraf[lb3d + 1 * DIM + d] = n;
    extraf[lb3d + 2 * DIM + d] = m;
}

// ---------------------------------------------------------------------------
// Launch. Inputs: input, h0, extra0, W0, b0, r0, W1, b1, r1
// Output: output[S,B,D] || h_f[L,B,D] || extra_f[L,B,3D]
// ---------------------------------------------------------------------------
extern "C" void kernel_launch(void* const* d_in, const int* in_sizes, int n_in,
                              void* d_out, int out_size)
{
    const float* input  = (const float*)d_in[0];
    const float* h0     = (const float*)d_in[1];
    const float* extra0 = (const float*)d_in[2];
    const float* W0     = (const float*)d_in[3];
    const float* b0     = (const float*)d_in[4];
    const float* r0     = (const float*)d_in[5];
    const float* W1     = (const float*)d_in[6];
    const float* b1     = (const float*)d_in[7];
    const float* r1     = (const float*)d_in[8];

    float* out    = (float*)d_out;
    float* hf     = out + (size_t)S_LEN * BATCH * DIM;
    float* extraf = hf + (size_t)2 * BATCH * DIM;

    float* pre;           cudaGetSymbolAddress((void**)&pre,  g_pre);
    __nv_bfloat16* ahi;   cudaGetSymbolAddress((void**)&ahi,  g_ahi);
    __nv_bfloat16* alo;   cudaGetSymbolAddress((void**)&alo,  g_alo);
    __nv_bfloat16* whi;   cudaGetSymbolAddress((void**)&whi,  g_whi);
    __nv_bfloat16* wlo;   cudaGetSymbolAddress((void**)&wlo,  g_wlo);

    cudaFuncSetAttribute(gemm_tc_kernel,
                         cudaFuncAttributeMaxDynamicSharedMemorySize, GEMM_SMEM);

    const int nA = MROWS * KDIM;   // 16.7M
    const int nW = GDIM * KDIM;    // 4.2M

    dim3 gemmGrid(GDIM / 128, MROWS / 128);   // (32, 128)
    dim3 scanGrid((BATCH * DIM) / 128);       // 128

    // ---- Layer 0 ----
    split_kernel<<<nA / 1024, 256>>>(input, ahi, alo, nA);
    split_kernel<<<nW / 1024, 256>>>(W0, whi, wlo, nW);
    gemm_tc_kernel<<<gemmGrid, 256, GEMM_SMEM>>>(ahi, alo, whi, wlo, b0, pre);
    // scan0 consumes pre; GEMM0 has fully consumed ahi/alo, so scan0 reuses them
    slstm_scan_kernel<true><<<scanGrid, 128>>>(pre, r0, h0, extra0, 0,
                                               nullptr, ahi, alo, hf, extraf);

    // ---- Layer 1 ----
    split_kernel<<<nW / 1024, 256>>>(W1, whi, wlo, nW);
    gemm_tc_kernel<<<gemmGrid, 256, GEMM_SMEM>>>(ahi, alo, whi, wlo, b1, pre);
    slstm_scan_kernel<false><<<scanGrid, 128>>>(pre, r1, h0, extra0, 1,
                                                out, nullptr, nullptr, hf, extraf);
}

// round 5
// speedup vs baseline: 5.2607x; 1.4238x over previous
#include <cuda_runtime.h>
#include <cuda_fp16.h>
#include <math.h>
#include <stdint.h>

// Problem constants (fixed: S=1024, B=16, I=D=1024, L=2)
#define S_LEN 1024
#define BATCH 16
#define DIM   1024
#define GDIM  (4 * DIM)       // 4096
#define KDIM  1024
#define MROWS (S_LEN * BATCH) // 16384
#define EPS 1e-6f

// ---------------------------------------------------------------------------
// Device scratch (no allocation allowed in kernel_launch)
// ---------------------------------------------------------------------------
__device__ float  g_pre[(size_t)S_LEN * BATCH * GDIM];  // 268 MB
__device__ __half g_ahi[(size_t)MROWS * KDIM];          // 33.5 MB
__device__ __half g_alo[(size_t)MROWS * KDIM];
__device__ __half g_whi[(size_t)GDIM * KDIM];           // 8.4 MB

// ---------------------------------------------------------------------------
// PTX helpers — base-target only (NO tcgen05: harness emits compute_103 PTX)
// ---------------------------------------------------------------------------
__device__ __forceinline__ uint32_t smem_u32(const void* p) {
    uint32_t a;
    asm("{ .reg .u64 t; cvta.to.shared.u64 t, %1; cvt.u32.u64 %0, t; }"
        : "=r"(a) : "l"(p));
    return a;
}
__device__ __forceinline__ void cp16(uint32_t dst, const void* src) {
    asm volatile("cp.async.cg.shared.global [%0], [%1], 16;"
                 :: "r"(dst), "l"(src));
}
__device__ __forceinline__ void ldsm_x4(uint32_t& r0, uint32_t& r1,
                                        uint32_t& r2, uint32_t& r3,
                                        uint32_t addr) {
    asm volatile("ldmatrix.sync.aligned.m8n8.x4.shared.b16 {%0,%1,%2,%3}, [%4];"
                 : "=r"(r0), "=r"(r1), "=r"(r2), "=r"(r3) : "r"(addr));
}
__device__ __forceinline__ void mma_f16(float* d, const uint32_t* a,
                                        uint32_t b0, uint32_t b1) {
    asm volatile(
        "mma.sync.aligned.m16n8k16.row.col.f32.f16.f16.f32 "
        "{%0,%1,%2,%3}, {%4,%5,%6,%7}, {%8,%9}, {%0,%1,%2,%3};"
        : "+f"(d[0]), "+f"(d[1]), "+f"(d[2]), "+f"(d[3])
        : "r"(a[0]), "r"(a[1]), "r"(a[2]), "r"(a[3]), "r"(b0), "r"(b1));
}

// Fast math (rel err ~2^-21; far under the 1e-3 budget)
__device__ __forceinline__ float fast_sigmoid(float x) {
    return __fdividef(1.0f, 1.0f + __expf(-x));
}
__device__ __forceinline__ float fast_tanh(float x) {
    float e = __expf(2.0f * x);
    return __fdividef(e - 1.0f, e + 1.0f);
}

// Swizzle: rows are 64B (32 fp16); XOR the 16B-segment index with (row>>1)&3
__device__ __forceinline__ uint32_t swz_addr(uint32_t plane_base, int row, int seg) {
    return plane_base + (uint32_t)(row * 64) + ((uint32_t)((seg ^ ((row >> 1) & 3)) << 4));
}

// ---------------------------------------------------------------------------
// fp32 -> (fp16 hi, fp16 lo) split kernel (for A). n multiple of 4.
// ---------------------------------------------------------------------------
__global__ __launch_bounds__(256)
void split_kernel(const float* __restrict__ src,
                  __half* __restrict__ hi,
                  __half* __restrict__ lo, int n)
{
    int i = (blockIdx.x * 256 + threadIdx.x) * 4;
    if (i >= n) return;
    float4 v = *reinterpret_cast<const float4*>(src + i);
    __half h0 = __float2half(v.x);
    __half h1 = __float2half(v.y);
    __half h2 = __float2half(v.z);
    __half h3 = __float2half(v.w);
    __half l0 = __float2half(v.x - __half2float(h0));
    __half l1 = __float2half(v.y - __half2float(h1));
    __half l2 = __float2half(v.z - __half2float(h2));
    __half l3 = __float2half(v.w - __half2float(h3));
    __half2* hi2 = reinterpret_cast<__half2*>(hi + i);
    __half2* lo2 = reinterpret_cast<__half2*>(lo + i);
    hi2[0] = __half2(h0, h1);
    hi2[1] = __half2(h2, h3);
    lo2[0] = __half2(l0, l1);
    lo2[1] = __half2(l2, l3);
}

// fp32 -> fp16 convert kernel (for W; no lo term needed in 2-term scheme)
__global__ __launch_bounds__(256)
void convert_kernel(const float* __restrict__ src,
                    __half* __restrict__ dst, int n)
{
    int i = (blockIdx.x * 256 + threadIdx.x) * 4;
    if (i >= n) return;
    float4 v = *reinterpret_cast<const float4*>(src + i);
    __half2* d2 = reinterpret_cast<__half2*>(dst + i);
    d2[0] = __half2(__float2half(v.x), __float2half(v.y));
    d2[1] = __half2(__float2half(v.z), __float2half(v.w));
}

// ---------------------------------------------------------------------------
// HMMA GEMM: C[M=16384, N=4096] = A[M,K=1024] @ W[N,K]^T + bias[N]
// fp32 via fp16 2-term: C = Ahi*Whi + Alo*Whi (fp32 accum).
// CTA 128x128, 8 warps (4M x 2N -> 32x64 warp tile), K-chunk 32,
// 3-stage cp.async pipeline (3 planes/stage = 24KB), 2 CTAs/SM.
// ---------------------------------------------------------------------------
#define KCHUNK 32
#define NCHUNK (KDIM / KCHUNK)       // 32
#define PLANE  8192                  // 128 rows * 64 bytes
#define STAGE_BYTES (3 * PLANE)      // Ahi, Alo, Whi = 24 KB
#define STAGES 3
#define GEMM_SMEM (STAGES * STAGE_BYTES)   // 72 KB

__device__ __forceinline__ void load_chunk(uint32_t stage_base,
                                           const __half* Ah,
                                           const __half* Al,
                                           const __half* Wh,
                                           int k0, int tid)
{
    // 3 planes x 128 rows x 4 segs(16B) = 1536 cp16 / 256 threads = 6 each.
#pragma unroll
    for (int p = 0; p < 3; p++) {
        const __half* src = (p == 0) ? Ah : (p == 1) ? Al : Wh;
#pragma unroll
        for (int h = 0; h < 2; h++) {
            int it = tid + h * 256;          // 0..511
            int row = it >> 2;
            int seg = it & 3;
            cp16(swz_addr(stage_base + p * PLANE, row, seg),
                 src + (size_t)row * KDIM + k0 + seg * 8);
        }
    }
}

__global__ __launch_bounds__(256, 2)
void gemm_tc_kernel(const __half* __restrict__ Ahi,
                    const __half* __restrict__ Alo,
                    const __half* __restrict__ Whi,
                    const float* __restrict__ bias,
                    float* __restrict__ C)
{
    extern __shared__ __align__(1024) char smem[];
    const uint32_t sbase = smem_u32(smem);
    const int tid  = threadIdx.x;
    const int wid  = tid >> 5;
    const int lane = tid & 31;
    const int warp_m = wid & 3;     // 4 warps in M: 32 rows each
    const int warp_n = wid >> 2;    // 2 warps in N: 64 cols each
    const int bm = blockIdx.y * 128;
    const int bn = blockIdx.x * 128;

    const __half* Ah = Ahi + (size_t)bm * KDIM;
    const __half* Al = Alo + (size_t)bm * KDIM;
    const __half* Wh = Whi + (size_t)bn * KDIM;

    float acc[2][8][4];
#pragma unroll
    for (int i = 0; i < 2; i++)
#pragma unroll
        for (int j = 0; j < 8; j++)
#pragma unroll
            for (int k = 0; k < 4; k++) acc[i][j][k] = 0.0f;

    load_chunk(sbase + 0 * STAGE_BYTES, Ah, Al, Wh, 0, tid);
    asm volatile("cp.async.commit_group;");
    load_chunk(sbase + 1 * STAGE_BYTES, Ah, Al, Wh, KCHUNK, tid);
    asm volatile("cp.async.commit_group;");

    const int a_lrow = lane & 15;
    const int a_lseg = lane >> 4;
    const int b_lrow = (lane & 7) + ((lane >> 4) << 3);
    const int b_lseg = (lane >> 3) & 1;

    for (int i = 0; i < NCHUNK; i++) {
        if (i + 1 < NCHUNK) { asm volatile("cp.async.wait_group 1;"); }
        else                { asm volatile("cp.async.wait_group 0;"); }
        __syncthreads();

        if (i + 2 < NCHUNK) {
            load_chunk(sbase + (uint32_t)((i + 2) % STAGES) * STAGE_BYTES,
                       Ah, Al, Wh, (i + 2) * KCHUNK, tid);
            asm volatile("cp.async.commit_group;");
        }

        const uint32_t st = sbase + (uint32_t)(i % STAGES) * STAGE_BYTES;

#pragma unroll
        for (int ks = 0; ks < 2; ks++) {
            uint32_t a[2][4], w[4][4];

            // W_hi fragments (shared by both passes)
#pragma unroll
            for (int jj = 0; jj < 4; jj++) {
                int row = warp_n * 64 + jj * 16 + b_lrow;
                ldsm_x4(w[jj][0], w[jj][1], w[jj][2], w[jj][3],
                        swz_addr(st + 2 * PLANE, row, ks * 2 + b_lseg));
            }
            // A_hi, hi * hi
#pragma unroll
            for (int ti = 0; ti < 2; ti++) {
                int row = warp_m * 32 + ti * 16 + a_lrow;
                ldsm_x4(a[ti][0], a[ti][1], a[ti][2], a[ti][3],
                        swz_addr(st + 0 * PLANE, row, ks * 2 + a_lseg));
            }
#pragma unroll
            for (int ti = 0; ti < 2; ti++)
#pragma unroll
                for (int jj = 0; jj < 4; jj++) {
                    mma_f16(acc[ti][2 * jj + 0], a[ti], w[jj][0], w[jj][1]);
                    mma_f16(acc[ti][2 * jj + 1], a[ti], w[jj][2], w[jj][3]);
                }
            // A_lo (reuse a regs), lo * hi
#pragma unroll
            for (int ti = 0; ti < 2; ti++) {
                int row = warp_m * 32 + ti * 16 + a_lrow;
                ldsm_x4(a[ti][0], a[ti][1], a[ti][2], a[ti][3],
                        swz_addr(st + 1 * PLANE, row, ks * 2 + a_lseg));
            }
#pragma unroll
            for (int ti = 0; ti < 2; ti++)
#pragma unroll
                for (int jj = 0; jj < 4; jj++) {
                    mma_f16(acc[ti][2 * jj + 0], a[ti], w[jj][0], w[jj][1]);
                    mma_f16(acc[ti][2 * jj + 1], a[ti], w[jj][2], w[jj][3]);
                }
        }
    }

    // Epilogue (streaming stores: C is read once by the scan, 268MB)
    const int mrow0 = bm + warp_m * 32 + (lane >> 2);
    const int col0  = bn + warp_n * 64 + (lane & 3) * 2;
#pragma unroll
    for (int ti = 0; ti < 2; ti++) {
#pragma unroll
        for (int g = 0; g < 8; g++) {
            int col = col0 + g * 8;
            float bb0 = bias[col];
            float bb1 = bias[col + 1];
            int r0 = mrow0 + ti * 16;
            float2 v0 = make_float2(acc[ti][g][0] + bb0, acc[ti][g][1] + bb1);
            float2 v1 = make_float2(acc[ti][g][2] + bb0, acc[ti][g][3] + bb1);
            __stcs(reinterpret_cast<float2*>(C + (size_t)r0 * GDIM + col), v0);
            __stcs(reinterpret_cast<float2*>(C + (size_t)(r0 + 8) * GDIM + col), v1);
        }
    }
}

// ---------------------------------------------------------------------------
// Elementwise sLSTM scan: fast math, depth-8 register prefetch (__ldcs),
// r==0 fast path. 64-thread blocks so all 148 SMs are used.
// EMIT_HALF: layer-0 writes h as fp16 hi/lo split (feeds GEMM1 directly).
// ---------------------------------------------------------------------------
#define PF 8

template <bool EMIT_HALF>
__global__ __launch_bounds__(64)
void slstm_scan_kernel(const float* __restrict__ pre,     // [S,B,4D]
                       const float* __restrict__ r,       // [4D]
                       const float* __restrict__ h0,      // [L,B,D]
                       const float* __restrict__ extra0,  // [L,B,3D]
                       int layer,
                       float* __restrict__ out_f32,       // [S,B,D] (or null)
                       __half* __restrict__ out_hi,
                       __half* __restrict__ out_lo,
                       float* __restrict__ hf,            // [L,B,D]
                       float* __restrict__ extraf)        // [L,B,3D]
{
    const int tid = blockIdx.x * 64 + threadIdx.x;   // 0..B*D-1
    const int d = tid & (DIM - 1);
    const int b = tid >> 10;

    const float rz = r[0 * DIM + d];
    const float ri = r[1 * DIM + d];
    const float rf = r[2 * DIM + d];
    const float ro = r[3 * DIM + d];
    const bool rzero = (rz == 0.0f) && (ri == 0.0f) && (rf == 0.0f) && (ro == 0.0f);

    const size_t lbd  = (size_t)layer * BATCH * DIM + (size_t)b * DIM;
    const size_t lb3d = (size_t)layer * BATCH * 3 * DIM + (size_t)b * 3 * DIM;

    float h = h0[lbd + d];
    float c = extra0[lb3d + 0 * DIM + d];
    float n = extra0[lb3d + 1 * DIM + d];
    float m = extra0[lb3d + 2 * DIM + d];

    const float* p = pre + (size_t)b * GDIM + d;
    const size_t strideT = (size_t)BATCH * GDIM;

    float pz[PF], pi_[PF], pf_[PF], po_[PF];
#pragma unroll
    for (int j = 0; j < PF; j++) {
        pz[j]  = __ldcs(p + 0 * DIM);
        pi_[j] = __ldcs(p + 1 * DIM);
        pf_[j] = __ldcs(p + 2 * DIM);
        po_[j] = __ldcs(p + 3 * DIM);
        p += strideT;
    }

    size_t outIdx = (size_t)b * DIM + d;
    const size_t strideO = (size_t)BATCH * DIM;

    if (rzero) {
        for (int t = 0; t < S_LEN; t += PF) {
            const bool more = (t + PF < S_LEN);
            float zt[PF], ot[PF], ip[PF], fp[PF];
#pragma unroll
            for (int j = 0; j < PF; j++) {
                zt[j] = fast_tanh(pz[j]);
                ot[j] = fast_sigmoid(po_[j]);
                ip[j] = pi_[j];
                fp[j] = pf_[j];
            }
            if (more) {
#pragma unroll
                for (int j = 0; j < PF; j++) {
                    pz[j]  = __ldcs(p + 0 * DIM);
                    pi_[j] = __ldcs(p + 1 * DIM);
                    pf_[j] = __ldcs(p + 2 * DIM);
                    po_[j] = __ldcs(p + 3 * DIM);
                    p += strideT;
                }
            }
#pragma unroll
            for (int j = 0; j < PF; j++) {
                const float fm = fp[j] + m;
                const float mn = fmaxf(fm, ip[j]);
                const float ft = __expf(fm - mn);
                const float it = __expf(ip[j] - mn);
                c = ft * c + it * zt[j];
                n = ft * n + it;
                m = mn;
                h = ot[j] * __fdividef(c, fabsf(n) + EPS);
                if (EMIT_HALF) {
                    __half hh = __float2half(h);
                    out_hi[outIdx] = hh;
                    out_lo[outIdx] = __float2half(h - __half2float(hh));
                } else {
                    out_f32[outIdx] = h;
                }
                outIdx += strideO;
            }
        }
    } else {
        for (int t = 0; t < S_LEN; t += PF) {
            const bool more = (t + PF < S_LEN);
            float bz[PF], bi[PF], bf4[PF], bo[PF];
#pragma unroll
            for (int j = 0; j < PF; j++) {
                bz[j] = pz[j]; bi[j] = pi_[j]; bf4[j] = pf_[j]; bo[j] = po_[j];
            }
            if (more) {
#pragma unroll
                for (int j = 0; j < PF; j++) {
                    pz[j]  = __ldcs(p + 0 * DIM);
                    pi_[j] = __ldcs(p + 1 * DIM);
                    pf_[j] = __ldcs(p + 2 * DIM);
                    po_[j] = __ldcs(p + 3 * DIM);
                    p += strideT;
                }
            }
#pragma unroll
            for (int j = 0; j < PF; j++) {
                const float zp = bz[j]  + rz * h;
                const float ip = bi[j]  + ri * h;
                const float fp = bf4[j] + rf * h;
                const float op = bo[j]  + ro * h;
                const float zt = fast_tanh(zp);
                const float ot = fast_sigmoid(op);
                const float fm = fp + m;
                const float mn = fmaxf(fm, ip);
                const float ft = __expf(fm - mn);
                const float it = __expf(ip - mn);
                c = ft * c + it * zt;
                n = ft * n + it;
                m = mn;
                h = ot * __fdividef(c, fabsf(n) + EPS);
                if (EMIT_HALF) {
                    __half hh = __float2half(h);
                    out_hi[outIdx] = hh;
                    out_lo[outIdx] = __float2half(h - __half2float(hh));
                } else {
                    out_f32[outIdx] = h;
                }
                outIdx += strideO;
            }
        }
    }

    hf[lbd + d] = h;
    extraf[lb3d + 0 * DIM + d] = c;
    extraf[lb3d + 1 * DIM + d] = n;
    extraf[lb3d + 2 * DIM + d] = m;
}

// ---------------------------------------------------------------------------
// Launch. Inputs: input, h0, extra0, W0, b0, r0, W1, b1, r1
// Output: output[S,B,D] || h_f[L,B,D] || extra_f[L,B,3D]
// ---------------------------------------------------------------------------
extern "C" void kernel_launch(void* const* d_in, const int* in_sizes, int n_in,
                              void* d_out, int out_size)
{
    const float* input  = (const float*)d_in[0];
    const float* h0     = (const float*)d_in[1];
    const float* extra0 = (const float*)d_in[2];
    const float* W0     = (const float*)d_in[3];
    const float* b0     = (const float*)d_in[4];
    const float* r0     = (const float*)d_in[5];
    const float* W1     = (const float*)d_in[6];
    const float* b1     = (const float*)d_in[7];
    const float* r1     = (const float*)d_in[8];

    float* out    = (float*)d_out;
    float* hf     = out + (size_t)S_LEN * BATCH * DIM;
    float* extraf = hf + (size_t)2 * BATCH * DIM;

    float* pre;   cudaGetSymbolAddress((void**)&pre, g_pre);
    __half* ahi;  cudaGetSymbolAddress((void**)&ahi, g_ahi);
    __half* alo;  cudaGetSymbolAddress((void**)&alo, g_alo);
    __half* whi;  cudaGetSymbolAddress((void**)&whi, g_whi);

    cudaFuncSetAttribute(gemm_tc_kernel,
                         cudaFuncAttributeMaxDynamicSharedMemorySize, GEMM_SMEM);

    const int nA = MROWS * KDIM;   // 16.7M
    const int nW = GDIM * KDIM;    // 4.2M

    dim3 gemmGrid(GDIM / 128, MROWS / 128);   // (32, 128)
    dim3 scanGrid((BATCH * DIM) / 64);        // 256

    // ---- Layer 0 ----
    split_kernel<<<nA / 1024, 256>>>(input, ahi, alo, nA);
    convert_kernel<<<nW / 1024, 256>>>(W0, whi, nW);
    gemm_tc_kernel<<<gemmGrid, 256, GEMM_SMEM>>>(ahi, alo, whi, b0, pre);
    // scan0 consumes pre; GEMM0 has fully consumed ahi/alo, so scan0 reuses them
    slstm_scan_kernel<true><<<scanGrid, 64>>>(pre, r0, h0, extra0, 0,
                                              nullptr, ahi, alo, hf, extraf);

    // ---- Layer 1 ----
    convert_kernel<<<nW / 1024, 256>>>(W1, whi, nW);
    gemm_tc_kernel<<<gemmGrid, 256, GEMM_SMEM>>>(ahi, alo, whi, b1, pre);
    slstm_scan_kernel<false><<<scanGrid, 64>>>(pre, r1, h0, extra0, 1,
                                               out, nullptr, nullptr, hf, extraf);
}

// round 6
// speedup vs baseline: 9.1974x; 1.7483x over previous
#include <cuda_runtime.h>
#include <cuda_fp16.h>
#include <math.h>
#include <stdint.h>

// Problem constants (fixed: S=1024, B=16, I=D=1024, L=2)
#define S_LEN 1024
#define BATCH 16
#define DIM   1024
#define GDIM  (4 * DIM)       // 4096
#define KDIM  1024
#define MROWS (S_LEN * BATCH) // 16384
#define EPS 1e-6f

// ---------------------------------------------------------------------------
// Device scratch (no allocation allowed in kernel_launch)
// ---------------------------------------------------------------------------
__device__ float  g_pre[(size_t)S_LEN * BATCH * GDIM];  // 268 MB
__device__ __half g_ah[(size_t)MROWS * KDIM];           // 33.5 MB (A in fp16)
__device__ __half g_wh[(size_t)GDIM * KDIM];            // 8.4 MB  (W in fp16)

// ---------------------------------------------------------------------------
// PTX helpers — base-target only (NO tcgen05: harness emits compute_103 PTX)
// ---------------------------------------------------------------------------
__device__ __forceinline__ uint32_t smem_u32(const void* p) {
    uint32_t a;
    asm("{ .reg .u64 t; cvta.to.shared.u64 t, %1; cvt.u32.u64 %0, t; }"
        : "=r"(a) : "l"(p));
    return a;
}
__device__ __forceinline__ void cp16(uint32_t dst, const void* src) {
    asm volatile("cp.async.cg.shared.global [%0], [%1], 16;"
                 :: "r"(dst), "l"(src));
}
__device__ __forceinline__ void ldsm_x4(uint32_t& r0, uint32_t& r1,
                                        uint32_t& r2, uint32_t& r3,
                                        uint32_t addr) {
    asm volatile("ldmatrix.sync.aligned.m8n8.x4.shared.b16 {%0,%1,%2,%3}, [%4];"
                 : "=r"(r0), "=r"(r1), "=r"(r2), "=r"(r3) : "r"(addr));
}
__device__ __forceinline__ void mma_f16(float* d, const uint32_t* a,
                                        uint32_t b0, uint32_t b1) {
    asm volatile(
        "mma.sync.aligned.m16n8k16.row.col.f32.f16.f16.f32 "
        "{%0,%1,%2,%3}, {%4,%5,%6,%7}, {%8,%9}, {%0,%1,%2,%3};"
        : "+f"(d[0]), "+f"(d[1]), "+f"(d[2]), "+f"(d[3])
        : "r"(a[0]), "r"(a[1]), "r"(a[2]), "r"(a[3]), "r"(b0), "r"(b1));
}

// Fast math (rel err ~2^-21; far under the 1e-3 budget)
__device__ __forceinline__ float fast_sigmoid(float x) {
    return __fdividef(1.0f, 1.0f + __expf(-x));
}
__device__ __forceinline__ float fast_tanh(float x) {
    float e = __expf(2.0f * x);
    return __fdividef(e - 1.0f, e + 1.0f);
}

// Swizzle: rows are 64B (32 fp16); XOR the 16B-segment index with (row>>1)&3
__device__ __forceinline__ uint32_t swz_addr(uint32_t plane_base, int row, int seg) {
    return plane_base + (uint32_t)(row * 64) + ((uint32_t)((seg ^ ((row >> 1) & 3)) << 4));
}

// ---------------------------------------------------------------------------
// fp32 -> fp16 convert kernel. n multiple of 4.
// ---------------------------------------------------------------------------
__global__ __launch_bounds__(256)
void convert_kernel(const float* __restrict__ src,
                    __half* __restrict__ dst, int n)
{
    int i = (blockIdx.x * 256 + threadIdx.x) * 4;
    if (i >= n) return;
    float4 v = *reinterpret_cast<const float4*>(src + i);
    __half2* d2 = reinterpret_cast<__half2*>(dst + i);
    d2[0] = __half2(__float2half(v.x), __float2half(v.y));
    d2[1] = __half2(__float2half(v.z), __float2half(v.w));
}

// ---------------------------------------------------------------------------
// HMMA GEMM: C[M=16384, N=4096] = A[M,K=1024] @ W[N,K]^T + bias[N]  (fp16 in,
// fp32 accum). CTA 128x128, 8 warps (4M x 2N), K-chunk 32, 4-stage cp.async
// pipeline (2 planes/stage = 16KB), 2 CTAs/SM.
// ---------------------------------------------------------------------------
#define KCHUNK 32
#define NCHUNK (KDIM / KCHUNK)       // 32
#define PLANE  8192                  // 128 rows * 64 bytes
#define STAGE_BYTES (2 * PLANE)      // A, W = 16 KB
#define STAGES 4
#define GEMM_SMEM (STAGES * STAGE_BYTES)   // 64 KB

__device__ __forceinline__ void load_chunk(uint32_t stage_base,
                                           const __half* Ap,
                                           const __half* Wp,
                                           int k0, int tid)
{
    // 2 planes x 128 rows x 4 segs(16B) = 1024 cp16 / 256 threads = 4 each.
#pragma unroll
    for (int p = 0; p < 2; p++) {
        const __half* src = (p == 0) ? Ap : Wp;
#pragma unroll
        for (int h = 0; h < 2; h++) {
            int it = tid + h * 256;          // 0..511
            int row = it >> 2;
            int seg = it & 3;
            cp16(swz_addr(stage_base + p * PLANE, row, seg),
                 src + (size_t)row * KDIM + k0 + seg * 8);
        }
    }
}

__global__ __launch_bounds__(256, 2)
void gemm_tc_kernel(const __half* __restrict__ Ah,
                    const __half* __restrict__ Wh,
                    const float* __restrict__ bias,
                    float* __restrict__ C)
{
    extern __shared__ __align__(1024) char smem[];
    const uint32_t sbase = smem_u32(smem);
    const int tid  = threadIdx.x;
    const int wid  = tid >> 5;
    const int lane = tid & 31;
    const int warp_m = wid & 3;     // 4 warps in M: 32 rows each
    const int warp_n = wid >> 2;    // 2 warps in N: 64 cols each
    const int bm = blockIdx.y * 128;
    const int bn = blockIdx.x * 128;

    const __half* Ap = Ah + (size_t)bm * KDIM;
    const __half* Wp = Wh + (size_t)bn * KDIM;

    float acc[2][8][4];
#pragma unroll
    for (int i = 0; i < 2; i++)
#pragma unroll
        for (int j = 0; j < 8; j++)
#pragma unroll
            for (int k = 0; k < 4; k++) acc[i][j][k] = 0.0f;

    // Prologue: stages 0,1,2
    load_chunk(sbase + 0 * STAGE_BYTES, Ap, Wp, 0 * KCHUNK, tid);
    asm volatile("cp.async.commit_group;");
    load_chunk(sbase + 1 * STAGE_BYTES, Ap, Wp, 1 * KCHUNK, tid);
    asm volatile("cp.async.commit_group;");
    load_chunk(sbase + 2 * STAGE_BYTES, Ap, Wp, 2 * KCHUNK, tid);
    asm volatile("cp.async.commit_group;");

    const int a_lrow = lane & 15;
    const int a_lseg = lane >> 4;
    const int b_lrow = (lane & 7) + ((lane >> 4) << 3);
    const int b_lseg = (lane >> 3) & 1;

    for (int i = 0; i < NCHUNK; i++) {
        const int rem = NCHUNK - 1 - i;
        if (rem >= 2)      { asm volatile("cp.async.wait_group 2;"); }
        else if (rem == 1) { asm volatile("cp.async.wait_group 1;"); }
        else               { asm volatile("cp.async.wait_group 0;"); }
        __syncthreads();

        if (i + 3 < NCHUNK) {
            load_chunk(sbase + (uint32_t)((i + 3) % STAGES) * STAGE_BYTES,
                       Ap, Wp, (i + 3) * KCHUNK, tid);
            asm volatile("cp.async.commit_group;");
        }

        const uint32_t st = sbase + (uint32_t)(i % STAGES) * STAGE_BYTES;

#pragma unroll
        for (int ks = 0; ks < 2; ks++) {
            uint32_t a[2][4], w[4][4];
#pragma unroll
            for (int jj = 0; jj < 4; jj++) {
                int row = warp_n * 64 + jj * 16 + b_lrow;
                ldsm_x4(w[jj][0], w[jj][1], w[jj][2], w[jj][3],
                        swz_addr(st + 1 * PLANE, row, ks * 2 + b_lseg));
            }
#pragma unroll
            for (int ti = 0; ti < 2; ti++) {
                int row = warp_m * 32 + ti * 16 + a_lrow;
                ldsm_x4(a[ti][0], a[ti][1], a[ti][2], a[ti][3],
                        swz_addr(st + 0 * PLANE, row, ks * 2 + a_lseg));
            }
#pragma unroll
            for (int ti = 0; ti < 2; ti++)
#pragma unroll
                for (int jj = 0; jj < 4; jj++) {
                    mma_f16(acc[ti][2 * jj + 0], a[ti], w[jj][0], w[jj][1]);
                    mma_f16(acc[ti][2 * jj + 1], a[ti], w[jj][2], w[jj][3]);
                }
        }
    }

    // Epilogue (streaming stores: C is read once by the scan, 268MB)
    const int mrow0 = bm + warp_m * 32 + (lane >> 2);
    const int col0  = bn + warp_n * 64 + (lane & 3) * 2;
#pragma unroll
    for (int ti = 0; ti < 2; ti++) {
#pragma unroll
        for (int g = 0; g < 8; g++) {
            int col = col0 + g * 8;
            float bb0 = bias[col];
            float bb1 = bias[col + 1];
            int r0 = mrow0 + ti * 16;
            float2 v0 = make_float2(acc[ti][g][0] + bb0, acc[ti][g][1] + bb1);
            float2 v1 = make_float2(acc[ti][g][2] + bb0, acc[ti][g][3] + bb1);
            __stcs(reinterpret_cast<float2*>(C + (size_t)r0 * GDIM + col), v0);
            __stcs(reinterpret_cast<float2*>(C + (size_t)(r0 + 8) * GDIM + col), v1);
        }
    }
}

// ---------------------------------------------------------------------------
// Elementwise sLSTM scan with cp.async smem staging (deep MLP, no register
// pressure). 64-thread blocks, 16-step double buffer (32KB static smem).
// EMIT_HALF: layer-0 writes h as fp16 (feeds GEMM1 A directly).
// ---------------------------------------------------------------------------
#define CH 16

template <bool EMIT_HALF>
__global__ __launch_bounds__(64)
void slstm_scan_kernel(const float* __restrict__ pre,     // [S,B,4D]
                       const float* __restrict__ r,       // [4D]
                       const float* __restrict__ h0,      // [L,B,D]
                       const float* __restrict__ extra0,  // [L,B,3D]
                       int layer,
                       float* __restrict__ out_f32,       // [S,B,D] (or null)
                       __half* __restrict__ out_h16,      // [S,B,D] (or null)
                       float* __restrict__ hf,            // [L,B,D]
                       float* __restrict__ extraf)        // [L,B,3D]
{
    __shared__ float buf[2][CH][4][64];   // 32 KB

    const int ltid = threadIdx.x;                 // 0..63
    const int L0 = blockIdx.x * 64;               // lane base (all same b)
    const int b  = L0 >> 10;
    const int d0 = L0 & (DIM - 1);
    const int d  = d0 + ltid;

    const float rz = r[0 * DIM + d];
    const float ri = r[1 * DIM + d];
    const float rf = r[2 * DIM + d];
    const float ro = r[3 * DIM + d];
    const bool rzero = (rz == 0.0f) && (ri == 0.0f) && (rf == 0.0f) && (ro == 0.0f);

    const size_t lbd  = (size_t)layer * BATCH * DIM + (size_t)b * DIM;
    const size_t lb3d = (size_t)layer * BATCH * 3 * DIM + (size_t)b * 3 * DIM;

    float h = h0[lbd + d];
    float c = extra0[lb3d + 0 * DIM + d];
    float n = extra0[lb3d + 1 * DIM + d];
    float m = extra0[lb3d + 2 * DIM + d];

    // Prefetch mapping: thread (g = ltid>>4, cc = ltid&15) fetches the 16B
    // chunk [cc*4 .. cc*4+3] of gate g for each of CH timesteps.
    const int g  = ltid >> 4;
    const int cc = ltid & 15;
    const size_t strideT = (size_t)BATCH * GDIM;
    const float* src0 = pre + (size_t)b * GDIM + (size_t)g * DIM + d0 + cc * 4;

#define SCAN_PREFETCH(stage, t0)                                              \
    do {                                                                      \
        const float* _s = src0 + (size_t)(t0) * strideT;                      \
        _Pragma("unroll")                                                     \
        for (int _j = 0; _j < CH; _j++) {                                     \
            cp16(smem_u32(&buf[stage][_j][g][cc * 4]), _s);                   \
            _s += strideT;                                                    \
        }                                                                     \
        asm volatile("cp.async.commit_group;");                               \
    } while (0)

    SCAN_PREFETCH(0, 0);
    SCAN_PREFETCH(1, CH);

    size_t outIdx = (size_t)b * DIM + d;
    const size_t strideO = (size_t)BATCH * DIM;

    int cur = 0;
    for (int t0 = 0; t0 < S_LEN; t0 += CH) {
        if (t0 + CH < S_LEN) { asm volatile("cp.async.wait_group 1;"); }
        else                 { asm volatile("cp.async.wait_group 0;"); }
        __syncthreads();

        if (rzero) {
            float zt[CH], ot[CH];
#pragma unroll
            for (int j = 0; j < CH; j++) {
                zt[j] = fast_tanh(buf[cur][j][0][ltid]);
                ot[j] = fast_sigmoid(buf[cur][j][3][ltid]);
            }
#pragma unroll
            for (int j = 0; j < CH; j++) {
                const float ip = buf[cur][j][1][ltid];
                const float fm = buf[cur][j][2][ltid] + m;
                const float mn = fmaxf(fm, ip);
                const float ft = __expf(fm - mn);
                const float it = __expf(ip - mn);
                c = ft * c + it * zt[j];
                n = ft * n + it;
                m = mn;
                h = ot[j] * __fdividef(c, fabsf(n) + EPS);
                if (EMIT_HALF) out_h16[outIdx] = __float2half(h);
                else           out_f32[outIdx] = h;
                outIdx += strideO;
            }
        } else {
#pragma unroll
            for (int j = 0; j < CH; j++) {
                const float zp = buf[cur][j][0][ltid] + rz * h;
                const float ip = buf[cur][j][1][ltid] + ri * h;
                const float fp = buf[cur][j][2][ltid] + rf * h;
                const float op = buf[cur][j][3][ltid] + ro * h;
                const float zt = fast_tanh(zp);
                const float ot = fast_sigmoid(op);
                const float fm = fp + m;
                const float mn = fmaxf(fm, ip);
                const float ft = __expf(fm - mn);
                const float it = __expf(ip - mn);
                c = ft * c + it * zt;
                n = ft * n + it;
                m = mn;
                h = ot * __fdividef(c, fabsf(n) + EPS);
                if (EMIT_HALF) out_h16[outIdx] = __float2half(h);
                else           out_f32[outIdx] = h;
                outIdx += strideO;
            }
        }
        __syncthreads();   // all reads of buf[cur] done before refill

        if (t0 + 2 * CH < S_LEN) {
            SCAN_PREFETCH(cur, t0 + 2 * CH);
        }
        cur ^= 1;
    }
#undef SCAN_PREFETCH

    hf[lbd + d] = h;
    extraf[lb3d + 0 * DIM + d] = c;
    extraf[lb3d + 1 * DIM + d] = n;
    extraf[lb3d + 2 * DIM + d] = m;
}

// ---------------------------------------------------------------------------
// Launch. Inputs: input, h0, extra0, W0, b0, r0, W1, b1, r1
// Output: output[S,B,D] || h_f[L,B,D] || extra_f[L,B,3D]
// ---------------------------------------------------------------------------
extern "C" void kernel_launch(void* const* d_in, const int* in_sizes, int n_in,
                              void* d_out, int out_size)
{
    const float* input  = (const float*)d_in[0];
    const float* h0     = (const float*)d_in[1];
    const float* extra0 = (const float*)d_in[2];
    const float* W0     = (const float*)d_in[3];
    const float* b0     = (const float*)d_in[4];
    const float* r0     = (const float*)d_in[5];
    const float* W1     = (const float*)d_in[6];
    const float* b1     = (const float*)d_in[7];
    const float* r1     = (const float*)d_in[8];

    float* out    = (float*)d_out;
    float* hf     = out + (size_t)S_LEN * BATCH * DIM;
    float* extraf = hf + (size_t)2 * BATCH * DIM;

    float* pre;  cudaGetSymbolAddress((void**)&pre, g_pre);
    __half* ah;  cudaGetSymbolAddress((void**)&ah,  g_ah);
    __half* wh;  cudaGetSymbolAddress((void**)&wh,  g_wh);

    cudaFuncSetAttribute(gemm_tc_kernel,
                         cudaFuncAttributeMaxDynamicSharedMemorySize, GEMM_SMEM);

    const int nA = MROWS * KDIM;   // 16.7M
    const int nW = GDIM * KDIM;    // 4.2M

    dim3 gemmGrid(GDIM / 128, MROWS / 128);   // (32, 128)
    dim3 scanGrid((BATCH * DIM) / 64);        // 256

    // ---- Layer 0 ----
    convert_kernel<<<nA / 1024, 256>>>(input, ah, nA);
    convert_kernel<<<nW / 1024, 256>>>(W0, wh, nW);
    gemm_tc_kernel<<<gemmGrid, 256, GEMM_SMEM>>>(ah, wh, b0, pre);
    // scan0 consumes pre; GEMM0 has fully consumed ah, so scan0 reuses it
    slstm_scan_kernel<true><<<scanGrid, 64>>>(pre, r0, h0, extra0, 0,
                                              nullptr, ah, hf, extraf);

    // ---- Layer 1 ----
    convert_kernel<<<nW / 1024, 256>>>(W1, wh, nW);
    gemm_tc_kernel<<<gemmGrid, 256, GEMM_SMEM>>>(ah, wh, b1, pre);
    slstm_scan_kernel<false><<<scanGrid, 64>>>(pre, r1, h0, extra0, 1,
                                               out, nullptr, hf, extraf);
}

// round 7
// speedup vs baseline: 9.4592x; 1.0285x over previous
#include <cuda_runtime.h>
#include <cuda_fp16.h>
#include <math.h>
#include <stdint.h>

// Problem constants (fixed: S=1024, B=16, I=D=1024, L=2)
#define S_LEN 1024
#define BATCH 16
#define DIM   1024
#define GDIM  (4 * DIM)       // 4096
#define KDIM  1024
#define MROWS (S_LEN * BATCH) // 16384
#define EPS 1e-6f

// ---------------------------------------------------------------------------
// Device scratch (no allocation allowed in kernel_launch)
// ---------------------------------------------------------------------------
__device__ float  g_pre[(size_t)S_LEN * BATCH * GDIM];  // 268 MB
__device__ __half g_ah[(size_t)MROWS * KDIM];           // 33.5 MB (A in fp16)
__device__ __half g_wh[(size_t)GDIM * KDIM];            // 8.4 MB  (W in fp16)

// ---------------------------------------------------------------------------
// PTX helpers — base-target only (NO tcgen05: harness emits compute_103 PTX)
// ---------------------------------------------------------------------------
__device__ __forceinline__ uint32_t smem_u32(const void* p) {
    uint32_t a;
    asm("{ .reg .u64 t; cvta.to.shared.u64 t, %1; cvt.u32.u64 %0, t; }"
        : "=r"(a) : "l"(p));
    return a;
}
__device__ __forceinline__ void cp16(uint32_t dst, const void* src) {
    asm volatile("cp.async.cg.shared.global [%0], [%1], 16;"
                 :: "r"(dst), "l"(src));
}
__device__ __forceinline__ void ldsm_x4(uint32_t& r0, uint32_t& r1,
                                        uint32_t& r2, uint32_t& r3,
                                        uint32_t addr) {
    asm volatile("ldmatrix.sync.aligned.m8n8.x4.shared.b16 {%0,%1,%2,%3}, [%4];"
                 : "=r"(r0), "=r"(r1), "=r"(r2), "=r"(r3) : "r"(addr));
}
__device__ __forceinline__ void mma_f16(float* d, const uint32_t* a,
                                        uint32_t b0, uint32_t b1) {
    asm volatile(
        "mma.sync.aligned.m16n8k16.row.col.f32.f16.f16.f32 "
        "{%0,%1,%2,%3}, {%4,%5,%6,%7}, {%8,%9}, {%0,%1,%2,%3};"
        : "+f"(d[0]), "+f"(d[1]), "+f"(d[2]), "+f"(d[3])
        : "r"(a[0]), "r"(a[1]), "r"(a[2]), "r"(a[3]), "r"(b0), "r"(b1));
}

// Fast math (rel err ~2^-21; far under the 1e-3 budget)
__device__ __forceinline__ float fast_sigmoid(float x) {
    return __fdividef(1.0f, 1.0f + __expf(-x));
}
__device__ __forceinline__ float fast_tanh(float x) {
    float e = __expf(2.0f * x);
    return __fdividef(e - 1.0f, e + 1.0f);
}

// Swizzle: rows are 64B (32 fp16); XOR the 16B-segment index with (row>>1)&3
__device__ __forceinline__ uint32_t swz_addr(uint32_t plane_base, int row, int seg) {
    return plane_base + (uint32_t)(row * 64) + ((uint32_t)((seg ^ ((row >> 1) & 3)) << 4));
}

// ---------------------------------------------------------------------------
// fp32 -> fp16 convert kernel. n multiple of 4.
// ---------------------------------------------------------------------------
__global__ __launch_bounds__(256)
void convert_kernel(const float* __restrict__ src,
                    __half* __restrict__ dst, int n)
{
    int i = (blockIdx.x * 256 + threadIdx.x) * 4;
    if (i >= n) return;
    float4 v = *reinterpret_cast<const float4*>(src + i);
    __half2* d2 = reinterpret_cast<__half2*>(dst + i);
    d2[0] = __half2(__float2half(v.x), __float2half(v.y));
    d2[1] = __half2(__float2half(v.z), __float2half(v.w));
}

// ---------------------------------------------------------------------------
// HMMA GEMM: C[M=16384, N=4096] = A[M,K=1024] @ W[N,K]^T + bias[N]  (fp16 in,
// fp32 accum). CTA 128x128, 8 warps (4M x 2N), K-chunk 64 (two 32-sub-chunks),
// 3-stage cp.async pipeline (32KB/stage), 2 CTAs/SM.
// ---------------------------------------------------------------------------
#define KCHUNK 64
#define NCHUNK (KDIM / KCHUNK)       // 16
#define PLANE  8192                  // 128 rows * 64 bytes (one 32-k sub-plane)
#define SUB_BYTES (2 * PLANE)        // [A, W] for one 32-k sub-chunk
#define STAGE_BYTES (2 * SUB_BYTES)  // 32 KB
#define STAGES 3
#define GEMM_SMEM (STAGES * STAGE_BYTES)   // 96 KB

__device__ __forceinline__ void load_chunk(uint32_t stage_base,
                                           const __half* Ap,
                                           const __half* Wp,
                                           int k0, int tid)
{
    // 2 subs x 2 planes x 128 rows x 4 segs(16B) = 2048 cp16 / 256 thr = 8 each
#pragma unroll
    for (int sub = 0; sub < 2; sub++) {
#pragma unroll
        for (int p = 0; p < 2; p++) {
            const __half* src = (p == 0) ? Ap : Wp;
#pragma unroll
            for (int h = 0; h < 2; h++) {
                int it = tid + h * 256;          // 0..511
                int row = it >> 2;
                int seg = it & 3;
                cp16(swz_addr(stage_base + sub * SUB_BYTES + p * PLANE, row, seg),
                     src + (size_t)row * KDIM + k0 + sub * 32 + seg * 8);
            }
        }
    }
}

__global__ __launch_bounds__(256, 2)
void gemm_tc_kernel(const __half* __restrict__ Ah,
                    const __half* __restrict__ Wh,
                    const float* __restrict__ bias,
                    float* __restrict__ C)
{
    extern __shared__ __align__(1024) char smem[];
    const uint32_t sbase = smem_u32(smem);
    const int tid  = threadIdx.x;
    const int wid  = tid >> 5;
    const int lane = tid & 31;
    const int warp_m = wid & 3;     // 4 warps in M: 32 rows each
    const int warp_n = wid >> 2;    // 2 warps in N: 64 cols each
    const int bm = blockIdx.y * 128;
    const int bn = blockIdx.x * 128;

    const __half* Ap = Ah + (size_t)bm * KDIM;
    const __half* Wp = Wh + (size_t)bn * KDIM;

    float acc[2][8][4];
#pragma unroll
    for (int i = 0; i < 2; i++)
#pragma unroll
        for (int j = 0; j < 8; j++)
#pragma unroll
            for (int k = 0; k < 4; k++) acc[i][j][k] = 0.0f;

    // Prologue: stages 0,1
    load_chunk(sbase + 0 * STAGE_BYTES, Ap, Wp, 0 * KCHUNK, tid);
    asm volatile("cp.async.commit_group;");
    load_chunk(sbase + 1 * STAGE_BYTES, Ap, Wp, 1 * KCHUNK, tid);
    asm volatile("cp.async.commit_group;");

    const int a_lrow = lane & 15;
    const int a_lseg = lane >> 4;
    const int b_lrow = (lane & 7) + ((lane >> 4) << 3);
    const int b_lseg = (lane >> 3) & 1;

    for (int i = 0; i < NCHUNK; i++) {
        if (i + 1 < NCHUNK) { asm volatile("cp.async.wait_group 1;"); }
        else                { asm volatile("cp.async.wait_group 0;"); }
        __syncthreads();

        if (i + 2 < NCHUNK) {
            load_chunk(sbase + (uint32_t)((i + 2) % STAGES) * STAGE_BYTES,
                       Ap, Wp, (i + 2) * KCHUNK, tid);
            asm volatile("cp.async.commit_group;");
        }

        const uint32_t st = sbase + (uint32_t)(i % STAGES) * STAGE_BYTES;

#pragma unroll
        for (int sub = 0; sub < 2; sub++) {
            const uint32_t base_a = st + sub * SUB_BYTES;
            const uint32_t base_w = base_a + PLANE;
#pragma unroll
            for (int ks = 0; ks < 2; ks++) {
                uint32_t a[2][4], w[4][4];
#pragma unroll
                for (int jj = 0; jj < 4; jj++) {
                    int row = warp_n * 64 + jj * 16 + b_lrow;
                    ldsm_x4(w[jj][0], w[jj][1], w[jj][2], w[jj][3],
                            swz_addr(base_w, row, ks * 2 + b_lseg));
                }
#pragma unroll
                for (int ti = 0; ti < 2; ti++) {
                    int row = warp_m * 32 + ti * 16 + a_lrow;
                    ldsm_x4(a[ti][0], a[ti][1], a[ti][2], a[ti][3],
                            swz_addr(base_a, row, ks * 2 + a_lseg));
                }
#pragma unroll
                for (int ti = 0; ti < 2; ti++)
#pragma unroll
                    for (int jj = 0; jj < 4; jj++) {
                        mma_f16(acc[ti][2 * jj + 0], a[ti], w[jj][0], w[jj][1]);
                        mma_f16(acc[ti][2 * jj + 1], a[ti], w[jj][2], w[jj][3]);
                    }
            }
        }
    }

    // Epilogue (streaming stores: C is read once by the scan, 268MB)
    const int mrow0 = bm + warp_m * 32 + (lane >> 2);
    const int col0  = bn + warp_n * 64 + (lane & 3) * 2;
#pragma unroll
    for (int ti = 0; ti < 2; ti++) {
#pragma unroll
        for (int g = 0; g < 8; g++) {
            int col = col0 + g * 8;
            float bb0 = bias[col];
            float bb1 = bias[col + 1];
            int r0 = mrow0 + ti * 16;
            float2 v0 = make_float2(acc[ti][g][0] + bb0, acc[ti][g][1] + bb1);
            float2 v1 = make_float2(acc[ti][g][2] + bb0, acc[ti][g][3] + bb1);
            __stcs(reinterpret_cast<float2*>(C + (size_t)r0 * GDIM + col), v0);
            __stcs(reinterpret_cast<float2*>(C + (size_t)(r0 + 8) * GDIM + col), v1);
        }
    }
}

// ---------------------------------------------------------------------------
// Elementwise sLSTM scan with cp.async smem staging, TRIPLE buffered
// (3 x 16-step tiles = 48 KB static smem). 64-thread blocks.
// EMIT_HALF: layer-0 writes h as fp16 (feeds GEMM1 A directly).
// ---------------------------------------------------------------------------
#define CH 16
#define NCH (S_LEN / CH)   // 64 chunks

template <bool EMIT_HALF>
__global__ __launch_bounds__(64)
void slstm_scan_kernel(const float* __restrict__ pre,     // [S,B,4D]
                       const float* __restrict__ r,       // [4D]
                       const float* __restrict__ h0,      // [L,B,D]
                       const float* __restrict__ extra0,  // [L,B,3D]
                       int layer,
                       float* __restrict__ out_f32,       // [S,B,D] (or null)
                       __half* __restrict__ out_h16,      // [S,B,D] (or null)
                       float* __restrict__ hf,            // [L,B,D]
                       float* __restrict__ extraf)        // [L,B,3D]
{
    __shared__ float buf[3][CH][4][64];   // 48 KB

    const int ltid = threadIdx.x;                 // 0..63
    const int L0 = blockIdx.x * 64;               // lane base (all same b)
    const int b  = L0 >> 10;
    const int d0 = L0 & (DIM - 1);
    const int d  = d0 + ltid;

    const float rz = r[0 * DIM + d];
    const float ri = r[1 * DIM + d];
    const float rf = r[2 * DIM + d];
    const float ro = r[3 * DIM + d];
    const bool rzero = (rz == 0.0f) && (ri == 0.0f) && (rf == 0.0f) && (ro == 0.0f);

    const size_t lbd  = (size_t)layer * BATCH * DIM + (size_t)b * DIM;
    const size_t lb3d = (size_t)layer * BATCH * 3 * DIM + (size_t)b * 3 * DIM;

    float h = h0[lbd + d];
    float c = extra0[lb3d + 0 * DIM + d];
    float n = extra0[lb3d + 1 * DIM + d];
    float m = extra0[lb3d + 2 * DIM + d];

    // Prefetch mapping: thread (g = ltid>>4, cc = ltid&15) fetches the 16B
    // chunk [cc*4 .. cc*4+3] of gate g for each of CH timesteps.
    const int g  = ltid >> 4;
    const int cc = ltid & 15;
    const size_t strideT = (size_t)BATCH * GDIM;
    const float* src0 = pre + (size_t)b * GDIM + (size_t)g * DIM + d0 + cc * 4;

#define SCAN_PREFETCH(stage, k)                                               \
    do {                                                                      \
        const float* _s = src0 + (size_t)(k) * CH * strideT;                  \
        _Pragma("unroll")                                                     \
        for (int _j = 0; _j < CH; _j++) {                                     \
            cp16(smem_u32(&buf[stage][_j][g][cc * 4]), _s);                   \
            _s += strideT;                                                    \
        }                                                                     \
        asm volatile("cp.async.commit_group;");                               \
    } while (0)

    SCAN_PREFETCH(0, 0);
    SCAN_PREFETCH(1, 1);
    SCAN_PREFETCH(2, 2);

    size_t outIdx = (size_t)b * DIM + d;
    const size_t strideO = (size_t)BATCH * DIM;

    for (int k = 0; k < NCH; k++) {
        // pending after chunk-k completes: chunks k+1, k+2 (if issued)
        if (k + 2 < NCH)      { asm volatile("cp.async.wait_group 2;"); }
        else if (k + 1 < NCH) { asm volatile("cp.async.wait_group 1;"); }
        else                  { asm volatile("cp.async.wait_group 0;"); }
        __syncthreads();

        const int cur = k % 3;

        if (rzero) {
            float zt[CH], ot[CH];
#pragma unroll
            for (int j = 0; j < CH; j++) {
                zt[j] = fast_tanh(buf[cur][j][0][ltid]);
                ot[j] = fast_sigmoid(buf[cur][j][3][ltid]);
            }
#pragma unroll
            for (int j = 0; j < CH; j++) {
                const float ip = buf[cur][j][1][ltid];
                const float fm = buf[cur][j][2][ltid] + m;
                const float mn = fmaxf(fm, ip);
                const float ft = __expf(fm - mn);
                const float it = __expf(ip - mn);
                c = ft * c + it * zt[j];
                n = ft * n + it;
                m = mn;
                h = ot[j] * __fdividef(c, fabsf(n) + EPS);
                if (EMIT_HALF) out_h16[outIdx] = __float2half(h);
                else           __stcs(out_f32 + outIdx, h);
                outIdx += strideO;
            }
        } else {
#pragma unroll
            for (int j = 0; j < CH; j++) {
                const float zp = buf[cur][j][0][ltid] + rz * h;
                const float ip = buf[cur][j][1][ltid] + ri * h;
                const float fp = buf[cur][j][2][ltid] + rf * h;
                const float op = buf[cur][j][3][ltid] + ro * h;
                const float zt = fast_tanh(zp);
                const float ot = fast_sigmoid(op);
                const float fm = fp + m;
                const float mn = fmaxf(fm, ip);
                const float ft = __expf(fm - mn);
                const float it = __expf(ip - mn);
                c = ft * c + it * zt;
                n = ft * n + it;
                m = mn;
                h = ot * __fdividef(c, fabsf(n) + EPS);
                if (EMIT_HALF) out_h16[outIdx] = __float2half(h);
                else           __stcs(out_f32 + outIdx, h);
                outIdx += strideO;
            }
        }
        __syncthreads();   // all reads of buf[cur] done before refill

        if (k + 3 < NCH) {
            SCAN_PREFETCH(cur, k + 3);
        }
    }
#undef SCAN_PREFETCH

    hf[lbd + d] = h;
    extraf[lb3d + 0 * DIM + d] = c;
    extraf[lb3d + 1 * DIM + d] = n;
    extraf[lb3d + 2 * DIM + d] = m;
}

// ---------------------------------------------------------------------------
// Launch. Inputs: input, h0, extra0, W0, b0, r0, W1, b1, r1
// Output: output[S,B,D] || h_f[L,B,D] || extra_f[L,B,3D]
// ---------------------------------------------------------------------------
extern "C" void kernel_launch(void* const* d_in, const int* in_sizes, int n_in,
                              void* d_out, int out_size)
{
    const float* input  = (const float*)d_in[0];
    const float* h0     = (const float*)d_in[1];
    const float* extra0 = (const float*)d_in[2];
    const float* W0     = (const float*)d_in[3];
    const float* b0     = (const float*)d_in[4];
    const float* r0     = (const float*)d_in[5];
    const float* W1     = (const float*)d_in[6];
    const float* b1     = (const float*)d_in[7];
    const float* r1     = (const float*)d_in[8];

    float* out    = (float*)d_out;
    float* hf     = out + (size_t)S_LEN * BATCH * DIM;
    float* extraf = hf + (size_t)2 * BATCH * DIM;

    float* pre;  cudaGetSymbolAddress((void**)&pre, g_pre);
    __half* ah;  cudaGetSymbolAddress((void**)&ah,  g_ah);
    __half* wh;  cudaGetSymbolAddress((void**)&wh,  g_wh);

    cudaFuncSetAttribute(gemm_tc_kernel,
                         cudaFuncAttributeMaxDynamicSharedMemorySize, GEMM_SMEM);

    const int nA = MROWS * KDIM;   // 16.7M
    const int nW = GDIM * KDIM;    // 4.2M

    dim3 gemmGrid(GDIM / 128, MROWS / 128);   // (32, 128)
    dim3 scanGrid((BATCH * DIM) / 64);        // 256

    // ---- Layer 0 ----
    convert_kernel<<<nA / 1024, 256>>>(input, ah, nA);
    convert_kernel<<<nW / 1024, 256>>>(W0, wh, nW);
    gemm_tc_kernel<<<gemmGrid, 256, GEMM_SMEM>>>(ah, wh, b0, pre);
    // scan0 consumes pre; GEMM0 has fully consumed ah, so scan0 reuses it
    slstm_scan_kernel<true><<<scanGrid, 64>>>(pre, r0, h0, extra0, 0,
                                              nullptr, ah, hf, extraf);

    // ---- Layer 1 ----
    convert_kernel<<<nW / 1024, 256>>>(W1, wh, nW);
    gemm_tc_kernel<<<gemmGrid, 256, GEMM_SMEM>>>(ah, wh, b1, pre);
    slstm_scan_kernel<false><<<scanGrid, 64>>>(pre, r1, h0, extra0, 1,
                                               out, nullptr, hf, extraf);
}

// round 8
// speedup vs baseline: 9.7047x; 1.0260x over previous
#include <cuda_runtime.h>
#include <cuda_fp16.h>
#include <math.h>
#include <stdint.h>

// Problem constants (fixed: S=1024, B=16, I=D=1024, L=2)
#define S_LEN 1024
#define BATCH 16
#define DIM   1024
#define GDIM  (4 * DIM)       // 4096
#define KDIM  1024
#define MROWS (S_LEN * BATCH) // 16384
#define EPS 1e-6f

// ---------------------------------------------------------------------------
// Device scratch (no allocation allowed in kernel_launch)
// ---------------------------------------------------------------------------
__device__ __half g_pre[(size_t)S_LEN * BATCH * GDIM];  // 134 MB (NO bias; fp16)
__device__ __half g_ah[(size_t)MROWS * KDIM];           // 33.5 MB (A in fp16)
__device__ __half g_wh0[(size_t)GDIM * KDIM];           // 8.4 MB  (W0 fp16)
__device__ __half g_wh1[(size_t)GDIM * KDIM];           // 8.4 MB  (W1 fp16)

// ---------------------------------------------------------------------------
// PTX helpers — base-target only (NO tcgen05: harness emits compute_103 PTX)
// ---------------------------------------------------------------------------
__device__ __forceinline__ uint32_t smem_u32(const void* p) {
    uint32_t a;
    asm("{ .reg .u64 t; cvta.to.shared.u64 t, %1; cvt.u32.u64 %0, t; }"
        : "=r"(a) : "l"(p));
    return a;
}
__device__ __forceinline__ void cp16(uint32_t dst, const void* src) {
    asm volatile("cp.async.cg.shared.global [%0], [%1], 16;"
                 :: "r"(dst), "l"(src));
}
__device__ __forceinline__ void ldsm_x4(uint32_t& r0, uint32_t& r1,
                                        uint32_t& r2, uint32_t& r3,
                                        uint32_t addr) {
    asm volatile("ldmatrix.sync.aligned.m8n8.x4.shared.b16 {%0,%1,%2,%3}, [%4];"
                 : "=r"(r0), "=r"(r1), "=r"(r2), "=r"(r3) : "r"(addr));
}
__device__ __forceinline__ void mma_f16(float* d, const uint32_t* a,
                                        uint32_t b0, uint32_t b1) {
    asm volatile(
        "mma.sync.aligned.m16n8k16.row.col.f32.f16.f16.f32 "
        "{%0,%1,%2,%3}, {%4,%5,%6,%7}, {%8,%9}, {%0,%1,%2,%3};"
        : "+f"(d[0]), "+f"(d[1]), "+f"(d[2]), "+f"(d[3])
        : "r"(a[0]), "r"(a[1]), "r"(a[2]), "r"(a[3]), "r"(b0), "r"(b1));
}

// Fast math (rel err ~2^-21; far under the 1e-3 budget)
__device__ __forceinline__ float fast_sigmoid(float x) {
    return __fdividef(1.0f, 1.0f + __expf(-x));
}
__device__ __forceinline__ float fast_tanh(float x) {
    float e = __expf(2.0f * x);
    return __fdividef(e - 1.0f, e + 1.0f);
}

// Swizzle: rows are 64B (32 fp16); XOR the 16B-segment index with (row>>1)&3
__device__ __forceinline__ uint32_t swz_addr(uint32_t plane_base, int row, int seg) {
    return plane_base + (uint32_t)(row * 64) + ((uint32_t)((seg ^ ((row >> 1) & 3)) << 4));
}

// ---------------------------------------------------------------------------
// fp32 -> fp16 convert kernel. n multiple of 4.
// ---------------------------------------------------------------------------
__global__ __launch_bounds__(256)
void convert_kernel(const float* __restrict__ src,
                    __half* __restrict__ dst, int n)
{
    int i = (blockIdx.x * 256 + threadIdx.x) * 4;
    if (i >= n) return;
    float4 v = *reinterpret_cast<const float4*>(src + i);
    __half2* d2 = reinterpret_cast<__half2*>(dst + i);
    d2[0] = __half2(__float2half(v.x), __float2half(v.y));
    d2[1] = __half2(__float2half(v.z), __float2half(v.w));
}

// ---------------------------------------------------------------------------
// HMMA GEMM: C[M=16384, N=4096] = A[M,K=1024] @ W[N,K]^T   (fp16 in/out,
// fp32 accum, NO bias — scan adds it in fp32). CTA 128x128, 8 warps,
// K-chunk 64, 3-stage cp.async pipeline (32KB/stage), 2 CTAs/SM.
// ---------------------------------------------------------------------------
#define KCHUNK 64
#define NCHUNK (KDIM / KCHUNK)       // 16
#define PLANE  8192                  // 128 rows * 64 bytes (one 32-k sub-plane)
#define SUB_BYTES (2 * PLANE)        // [A, W] for one 32-k sub-chunk
#define STAGE_BYTES (2 * SUB_BYTES)  // 32 KB
#define STAGES 3
#define GEMM_SMEM (STAGES * STAGE_BYTES)   // 96 KB

__device__ __forceinline__ void load_chunk(uint32_t stage_base,
                                           const __half* Ap,
                                           const __half* Wp,
                                           int k0, int tid)
{
#pragma unroll
    for (int sub = 0; sub < 2; sub++) {
#pragma unroll
        for (int p = 0; p < 2; p++) {
            const __half* src = (p == 0) ? Ap : Wp;
#pragma unroll
            for (int h = 0; h < 2; h++) {
                int it = tid + h * 256;          // 0..511
                int row = it >> 2;
                int seg = it & 3;
                cp16(swz_addr(stage_base + sub * SUB_BYTES + p * PLANE, row, seg),
                     src + (size_t)row * KDIM + k0 + sub * 32 + seg * 8);
            }
        }
    }
}

__global__ __launch_bounds__(256, 2)
void gemm_tc_kernel(const __half* __restrict__ Ah,
                    const __half* __restrict__ Wh,
                    __half* __restrict__ C)
{
    extern __shared__ __align__(1024) char smem[];
    const uint32_t sbase = smem_u32(smem);
    const int tid  = threadIdx.x;
    const int wid  = tid >> 5;
    const int lane = tid & 31;
    const int warp_m = wid & 3;     // 4 warps in M: 32 rows each
    const int warp_n = wid >> 2;    // 2 warps in N: 64 cols each
    const int bm = blockIdx.y * 128;
    const int bn = blockIdx.x * 128;

    const __half* Ap = Ah + (size_t)bm * KDIM;
    const __half* Wp = Wh + (size_t)bn * KDIM;

    float acc[2][8][4];
#pragma unroll
    for (int i = 0; i < 2; i++)
#pragma unroll
        for (int j = 0; j < 8; j++)
#pragma unroll
            for (int k = 0; k < 4; k++) acc[i][j][k] = 0.0f;

    load_chunk(sbase + 0 * STAGE_BYTES, Ap, Wp, 0 * KCHUNK, tid);
    asm volatile("cp.async.commit_group;");
    load_chunk(sbase + 1 * STAGE_BYTES, Ap, Wp, 1 * KCHUNK, tid);
    asm volatile("cp.async.commit_group;");

    const int a_lrow = lane & 15;
    const int a_lseg = lane >> 4;
    const int b_lrow = (lane & 7) + ((lane >> 4) << 3);
    const int b_lseg = (lane >> 3) & 1;

    for (int i = 0; i < NCHUNK; i++) {
        if (i + 1 < NCHUNK) { asm volatile("cp.async.wait_group 1;"); }
        else                { asm volatile("cp.async.wait_group 0;"); }
        __syncthreads();

        if (i + 2 < NCHUNK) {
            load_chunk(sbase + (uint32_t)((i + 2) % STAGES) * STAGE_BYTES,
                       Ap, Wp, (i + 2) * KCHUNK, tid);
            asm volatile("cp.async.commit_group;");
        }

        const uint32_t st = sbase + (uint32_t)(i % STAGES) * STAGE_BYTES;

#pragma unroll
        for (int sub = 0; sub < 2; sub++) {
            const uint32_t base_a = st + sub * SUB_BYTES;
            const uint32_t base_w = base_a + PLANE;
#pragma unroll
            for (int ks = 0; ks < 2; ks++) {
                uint32_t a[2][4], w[4][4];
#pragma unroll
                for (int jj = 0; jj < 4; jj++) {
                    int row = warp_n * 64 + jj * 16 + b_lrow;
                    ldsm_x4(w[jj][0], w[jj][1], w[jj][2], w[jj][3],
                            swz_addr(base_w, row, ks * 2 + b_lseg));
                }
#pragma unroll
                for (int ti = 0; ti < 2; ti++) {
                    int row = warp_m * 32 + ti * 16 + a_lrow;
                    ldsm_x4(a[ti][0], a[ti][1], a[ti][2], a[ti][3],
                            swz_addr(base_a, row, ks * 2 + a_lseg));
                }
#pragma unroll
                for (int ti = 0; ti < 2; ti++)
#pragma unroll
                    for (int jj = 0; jj < 4; jj++) {
                        mma_f16(acc[ti][2 * jj + 0], a[ti], w[jj][0], w[jj][1]);
                        mma_f16(acc[ti][2 * jj + 1], a[ti], w[jj][2], w[jj][3]);
                    }
            }
        }
    }

    // Epilogue: fp16 streaming stores (C read once by the scan; 134MB)
    const int mrow0 = bm + warp_m * 32 + (lane >> 2);
    const int col0  = bn + warp_n * 64 + (lane & 3) * 2;
#pragma unroll
    for (int ti = 0; ti < 2; ti++) {
#pragma unroll
        for (int g = 0; g < 8; g++) {
            int col = col0 + g * 8;
            int r0 = mrow0 + ti * 16;
            __half2 v0 = __floats2half2_rn(acc[ti][g][0], acc[ti][g][1]);
            __half2 v1 = __floats2half2_rn(acc[ti][g][2], acc[ti][g][3]);
            __stcs(reinterpret_cast<__half2*>(C + (size_t)r0 * GDIM + col), v0);
            __stcs(reinterpret_cast<__half2*>(C + (size_t)(r0 + 8) * GDIM + col), v1);
        }
    }
}

// ---------------------------------------------------------------------------
// Elementwise sLSTM scan: fp16 pre (bias-free) staged via cp.async, triple
// buffered (3 x 16-step tiles = 24 KB). Bias added in fp32 here.
// EMIT_HALF: layer-0 writes h as fp16 (feeds GEMM1 A directly).
// ---------------------------------------------------------------------------
#define CH 16
#define NCH (S_LEN / CH)   // 64 chunks

template <bool EMIT_HALF>
__global__ __launch_bounds__(64)
void slstm_scan_kernel(const __half* __restrict__ pre,    // [S,B,4D] (no bias)
                       const float* __restrict__ bias,    // [4D]
                       const float* __restrict__ r,       // [4D]
                       const float* __restrict__ h0,      // [L,B,D]
                       const float* __restrict__ extra0,  // [L,B,3D]
                       int layer,
                       float* __restrict__ out_f32,       // [S,B,D] (or null)
                       __half* __restrict__ out_h16,      // [S,B,D] (or null)
                       float* __restrict__ hf,            // [L,B,D]
                       float* __restrict__ extraf)        // [L,B,3D]
{
    __shared__ __half buf[3][CH][4][64];   // 24 KB

    const int ltid = threadIdx.x;                 // 0..63
    const int L0 = blockIdx.x * 64;               // lane base (all same b)
    const int b  = L0 >> 10;
    const int d0 = L0 & (DIM - 1);
    const int d  = d0 + ltid;

    const float rz = r[0 * DIM + d];
    const float ri = r[1 * DIM + d];
    const float rf = r[2 * DIM + d];
    const float ro = r[3 * DIM + d];
    const float bz = bias[0 * DIM + d];
    const float bi = bias[1 * DIM + d];
    const float bf = bias[2 * DIM + d];
    const float bo = bias[3 * DIM + d];
    const bool rzero = (rz == 0.0f) && (ri == 0.0f) && (rf == 0.0f) && (ro == 0.0f);

    const size_t lbd  = (size_t)layer * BATCH * DIM + (size_t)b * DIM;
    const size_t lb3d = (size_t)layer * BATCH * 3 * DIM + (size_t)b * 3 * DIM;

    float h = h0[lbd + d];
    float c = extra0[lb3d + 0 * DIM + d];
    float n = extra0[lb3d + 1 * DIM + d];
    float m = extra0[lb3d + 2 * DIM + d];

    // Prefetch mapping: g = gate (0..3), cc = 16B chunk (0..7: lanes cc*8..+7),
    // sh = step parity. Each thread issues CH/2 cp16 per chunk.
    const int g  = ltid >> 4;
    const int cc = ltid & 7;
    const int sh = (ltid >> 3) & 1;
    const size_t strideT = (size_t)BATCH * GDIM;
    const __half* src0 = pre + (size_t)b * GDIM + (size_t)g * DIM + d0 + cc * 8;

#define SCAN_PREFETCH(stage, k)                                               \
    do {                                                                      \
        const __half* _s = src0 + ((size_t)(k) * CH + sh) * strideT;          \
        _Pragma("unroll")                                                     \
        for (int _jj = 0; _jj < CH / 2; _jj++) {                              \
            cp16(smem_u32(&buf[stage][2 * _jj + sh][g][cc * 8]), _s);         \
            _s += 2 * strideT;                                                \
        }                                                                     \
        asm volatile("cp.async.commit_group;");                               \
    } while (0)

    SCAN_PREFETCH(0, 0);
    SCAN_PREFETCH(1, 1);
    SCAN_PREFETCH(2, 2);

    size_t outIdx = (size_t)b * DIM + d;
    const size_t strideO = (size_t)BATCH * DIM;

    for (int k = 0; k < NCH; k++) {
        if (k + 2 < NCH)      { asm volatile("cp.async.wait_group 2;"); }
        else if (k + 1 < NCH) { asm volatile("cp.async.wait_group 1;"); }
        else                  { asm volatile("cp.async.wait_group 0;"); }
        __syncthreads();

        const int cur = k % 3;

        if (rzero) {
            float zt[CH], ot[CH];
#pragma unroll
            for (int j = 0; j < CH; j++) {
                zt[j] = fast_tanh(__half2float(buf[cur][j][0][ltid]) + bz);
                ot[j] = fast_sigmoid(__half2float(buf[cur][j][3][ltid]) + bo);
            }
#pragma unroll
            for (int j = 0; j < CH; j++) {
                const float ip = __half2float(buf[cur][j][1][ltid]) + bi;
                const float fm = __half2float(buf[cur][j][2][ltid]) + bf + m;
                const float mn = fmaxf(fm, ip);
                const float ft = __expf(fm - mn);
                const float it = __expf(ip - mn);
                c = ft * c + it * zt[j];
                n = ft * n + it;
                m = mn;
                h = ot[j] * __fdividef(c, fabsf(n) + EPS);
                if (EMIT_HALF) out_h16[outIdx] = __float2half(h);
                else           __stcs(out_f32 + outIdx, h);
                outIdx += strideO;
            }
        } else {
#pragma unroll
            for (int j = 0; j < CH; j++) {
                const float zp = __half2float(buf[cur][j][0][ltid]) + bz + rz * h;
                const float ip = __half2float(buf[cur][j][1][ltid]) + bi + ri * h;
                const float fp = __half2float(buf[cur][j][2][ltid]) + bf + rf * h;
                const float op = __half2float(buf[cur][j][3][ltid]) + bo + ro * h;
                const float zt = fast_tanh(zp);
                const float ot = fast_sigmoid(op);
                const float fm = fp + m;
                const float mn = fmaxf(fm, ip);
                const float ft = __expf(fm - mn);
                const float it = __expf(ip - mn);
                c = ft * c + it * zt;
                n = ft * n + it;
                m = mn;
                h = ot * __fdividef(c, fabsf(n) + EPS);
                if (EMIT_HALF) out_h16[outIdx] = __float2half(h);
                else           __stcs(out_f32 + outIdx, h);
                outIdx += strideO;
            }
        }
        __syncthreads();   // all reads of buf[cur] done before refill

        if (k + 3 < NCH) {
            SCAN_PREFETCH(cur, k + 3);
        }
    }
#undef SCAN_PREFETCH

    hf[lbd + d] = h;
    extraf[lb3d + 0 * DIM + d] = c;
    extraf[lb3d + 1 * DIM + d] = n;
    extraf[lb3d + 2 * DIM + d] = m;
}

// ---------------------------------------------------------------------------
// Launch. Inputs: input, h0, extra0, W0, b0, r0, W1, b1, r1
// Output: output[S,B,D] || h_f[L,B,D] || extra_f[L,B,3D]
// ---------------------------------------------------------------------------
extern "C" void kernel_launch(void* const* d_in, const int* in_sizes, int n_in,
                              void* d_out, int out_size)
{
    const float* input  = (const float*)d_in[0];
    const float* h0     = (const float*)d_in[1];
    const float* extra0 = (const float*)d_in[2];
    const float* W0     = (const float*)d_in[3];
    const float* b0     = (const float*)d_in[4];
    const float* r0     = (const float*)d_in[5];
    const float* W1     = (const float*)d_in[6];
    const float* b1     = (const float*)d_in[7];
    const float* r1     = (const float*)d_in[8];

    float* out    = (float*)d_out;
    float* hf     = out + (size_t)S_LEN * BATCH * DIM;
    float* extraf = hf + (size_t)2 * BATCH * DIM;

    __half* pre;  cudaGetSymbolAddress((void**)&pre, g_pre);
    __half* ah;   cudaGetSymbolAddress((void**)&ah,  g_ah);
    __half* wh0;  cudaGetSymbolAddress((void**)&wh0, g_wh0);
    __half* wh1;  cudaGetSymbolAddress((void**)&wh1, g_wh1);

    cudaFuncSetAttribute(gemm_tc_kernel,
                         cudaFuncAttributeMaxDynamicSharedMemorySize, GEMM_SMEM);

    const int nA = MROWS * KDIM;   // 16.7M
    const int nW = GDIM * KDIM;    // 4.2M

    dim3 gemmGrid(GDIM / 128, MROWS / 128);   // (32, 128)
    dim3 scanGrid((BATCH * DIM) / 64);        // 256

    // All converts up front (wh1 is independent of layer-0's pipeline)
    convert_kernel<<<nA / 1024, 256>>>(input, ah, nA);
    convert_kernel<<<nW / 1024, 256>>>(W0, wh0, nW);
    convert_kernel<<<nW / 1024, 256>>>(W1, wh1, nW);

    // ---- Layer 0 ----
    gemm_tc_kernel<<<gemmGrid, 256, GEMM_SMEM>>>(ah, wh0, pre);
    slstm_scan_kernel<true><<<scanGrid, 64>>>(pre, b0, r0, h0, extra0, 0,
                                              nullptr, ah, hf, extraf);

    // ---- Layer 1 ----
    gemm_tc_kernel<<<gemmGrid, 256, GEMM_SMEM>>>(ah, wh1, pre);
    slstm_scan_kernel<false><<<scanGrid, 64>>>(pre, b1, r1, h0, extra0, 1,
                                               out, nullptr, hf, extraf);
}